// round 1
// baseline (speedup 1.0000x reference)
#include <cuda_runtime.h>
#include <math.h>

#define Bd 8
#define Nd 2048
#define Cd 768
#define Hd 12
#define HDd 64
#define SCALEf 0.125f

// ---------------- scratch (device globals; no allocation allowed) ----------
__device__ float g_q[Bd * Hd * Nd * HDd];   // [B,H,N,HD]
__device__ float g_k[Bd * Hd * Nd * HDd];
__device__ float g_v[Bd * Hd * Nd * HDd];
__device__ float g_ao[Bd * Nd * Cd];        // attention output, [B,N,C]

// ---------------- tiled GEMM: y[m,d] = sum_c A[m,c] * W[d,c] + bias[d] -----
// Tile 64x64x16, 256 threads, 4x4 micro-tile. Tiles stored transposed in smem.
#define TM 64
#define TN 64
#define TK 16

__global__ __launch_bounds__(256)
void gemm_qkv_kernel(const float* __restrict__ x,
                     const float* __restrict__ wq, const float* __restrict__ wk,
                     const float* __restrict__ wv,
                     const float* __restrict__ bq, const float* __restrict__ bk,
                     const float* __restrict__ bv)
{
    __shared__ float xs[TK][TM];
    __shared__ float ws[TK][TN];

    const int z = blockIdx.z;
    const float* W    = (z == 0) ? wq : (z == 1) ? wk : wv;
    const float* bias = (z == 0) ? bq : (z == 1) ? bk : bv;
    float* outp       = (z == 0) ? g_q : (z == 1) ? g_k : g_v;

    const int m0 = blockIdx.y * TM;
    const int n0 = blockIdx.x * TN;
    const int tid = threadIdx.x;
    const int tx = tid & 15;
    const int ty = tid >> 4;

    // load mapping: each thread loads one float4 of each tile
    const int lr = tid >> 2;          // 0..63 row
    const int lc = (tid & 3) * 4;     // 0,4,8,12 col

    float acc[4][4] = {};

    for (int k0 = 0; k0 < Cd; k0 += TK) {
        float4 xa = *(const float4*)&x[(size_t)(m0 + lr) * Cd + k0 + lc];
        float4 wa = *(const float4*)&W[(size_t)(n0 + lr) * Cd + k0 + lc];
        xs[lc + 0][lr] = xa.x; xs[lc + 1][lr] = xa.y;
        xs[lc + 2][lr] = xa.z; xs[lc + 3][lr] = xa.w;
        ws[lc + 0][lr] = wa.x; ws[lc + 1][lr] = wa.y;
        ws[lc + 2][lr] = wa.z; ws[lc + 3][lr] = wa.w;
        __syncthreads();

        #pragma unroll
        for (int kk = 0; kk < TK; kk++) {
            float4 a4 = *(const float4*)&xs[kk][ty * 4];
            float4 b4 = *(const float4*)&ws[kk][tx * 4];
            float a[4] = {a4.x, a4.y, a4.z, a4.w};
            float b[4] = {b4.x, b4.y, b4.z, b4.w};
            #pragma unroll
            for (int i = 0; i < 4; i++)
                #pragma unroll
                for (int j = 0; j < 4; j++)
                    acc[i][j] += a[i] * b[j];
        }
        __syncthreads();
    }

    // scatter to [B,H,N,HD]
    #pragma unroll
    for (int i = 0; i < 4; i++) {
        const int m = m0 + ty * 4 + i;
        const int bb = m >> 11;         // /2048
        const int n  = m & 2047;
        #pragma unroll
        for (int j = 0; j < 4; j++) {
            const int d = n0 + tx * 4 + j;
            const int h  = d >> 6;
            const int hd = d & 63;
            outp[(((size_t)(bb * Hd + h)) * Nd + n) * HDd + hd] = acc[i][j] + bias[d];
        }
    }
}

__global__ __launch_bounds__(256)
void gemm_o_kernel(const float* __restrict__ W,
                   const float* __restrict__ bias,
                   float* __restrict__ out)
{
    __shared__ float xs[TK][TM];
    __shared__ float ws[TK][TN];

    const int m0 = blockIdx.y * TM;
    const int n0 = blockIdx.x * TN;
    const int tid = threadIdx.x;
    const int tx = tid & 15;
    const int ty = tid >> 4;
    const int lr = tid >> 2;
    const int lc = (tid & 3) * 4;

    float acc[4][4] = {};

    for (int k0 = 0; k0 < Cd; k0 += TK) {
        float4 xa = *(const float4*)&g_ao[(size_t)(m0 + lr) * Cd + k0 + lc];
        float4 wa = *(const float4*)&W[(size_t)(n0 + lr) * Cd + k0 + lc];
        xs[lc + 0][lr] = xa.x; xs[lc + 1][lr] = xa.y;
        xs[lc + 2][lr] = xa.z; xs[lc + 3][lr] = xa.w;
        ws[lc + 0][lr] = wa.x; ws[lc + 1][lr] = wa.y;
        ws[lc + 2][lr] = wa.z; ws[lc + 3][lr] = wa.w;
        __syncthreads();

        #pragma unroll
        for (int kk = 0; kk < TK; kk++) {
            float4 a4 = *(const float4*)&xs[kk][ty * 4];
            float4 b4 = *(const float4*)&ws[kk][tx * 4];
            float a[4] = {a4.x, a4.y, a4.z, a4.w};
            float b[4] = {b4.x, b4.y, b4.z, b4.w};
            #pragma unroll
            for (int i = 0; i < 4; i++)
                #pragma unroll
                for (int j = 0; j < 4; j++)
                    acc[i][j] += a[i] * b[j];
        }
        __syncthreads();
    }

    #pragma unroll
    for (int i = 0; i < 4; i++) {
        const int m = m0 + ty * 4 + i;
        #pragma unroll
        for (int j = 0; j < 4; j++) {
            const int d = n0 + tx * 4 + j;
            out[(size_t)m * Cd + d] = acc[i][j] + bias[d];
        }
    }
}

// ---------------- attention -----------------------------------------------
// One thread per query row. No online max: scores are bounded (~|s|<25),
// exp() in fp32 cannot overflow, so p = exp(s) directly; out = acc / l.
#define AT_ROWS 128
#define AT_TK   64

__global__ __launch_bounds__(AT_ROWS)
void attn_kernel(const float* __restrict__ size)
{
    __shared__ float ks[AT_TK][HDd];
    __shared__ float vs[AT_TK][HDd];
    __shared__ float bias_s[AT_TK];

    const int bh = blockIdx.x;            // 0..95
    const int b  = bh / Hd;
    const int h  = bh % Hd;
    const int tid = threadIdx.x;
    const int qi = blockIdx.y * AT_ROWS + tid;

    const float* qp = &g_q[((size_t)bh * Nd + qi) * HDd];
    float q[HDd];
    #pragma unroll
    for (int d = 0; d < HDd; d += 4) {
        float4 t = *(const float4*)&qp[d];
        q[d] = t.x; q[d + 1] = t.y; q[d + 2] = t.z; q[d + 3] = t.w;
    }

    float acc[HDd];
    #pragma unroll
    for (int d = 0; d < HDd; d++) acc[d] = 0.f;
    float l = 0.f;

    const float* kbase = &g_k[(size_t)bh * Nd * HDd];
    const float* vbase = &g_v[(size_t)bh * Nd * HDd];
    const float* sbase = &size[(size_t)b * Nd];

    for (int k0 = 0; k0 < Nd; k0 += AT_TK) {
        __syncthreads();
        // contiguous 4096-float tile copy, 128 threads x 8 float4
        const float4* kt = (const float4*)(kbase + (size_t)k0 * HDd);
        const float4* vt = (const float4*)(vbase + (size_t)k0 * HDd);
        float4* ksf = (float4*)&ks[0][0];
        float4* vsf = (float4*)&vs[0][0];
        #pragma unroll
        for (int i = 0; i < 8; i++) {
            ksf[tid + i * AT_ROWS] = kt[tid + i * AT_ROWS];
            vsf[tid + i * AT_ROWS] = vt[tid + i * AT_ROWS];
        }
        if (tid < AT_TK) bias_s[tid] = __logf(sbase[k0 + tid]);
        __syncthreads();

        #pragma unroll 2
        for (int j = 0; j < AT_TK; j++) {
            float s = 0.f;
            #pragma unroll
            for (int d4 = 0; d4 < HDd / 4; d4++) {
                float4 kv = *(const float4*)&ks[j][d4 * 4];
                s += q[d4 * 4 + 0] * kv.x;
                s += q[d4 * 4 + 1] * kv.y;
                s += q[d4 * 4 + 2] * kv.z;
                s += q[d4 * 4 + 3] * kv.w;
            }
            float p = __expf(s * SCALEf + bias_s[j]);
            l += p;
            #pragma unroll
            for (int d4 = 0; d4 < HDd / 4; d4++) {
                float4 vv = *(const float4*)&vs[j][d4 * 4];
                acc[d4 * 4 + 0] += p * vv.x;
                acc[d4 * 4 + 1] += p * vv.y;
                acc[d4 * 4 + 2] += p * vv.z;
                acc[d4 * 4 + 3] += p * vv.w;
            }
        }
    }

    const float inv = 1.f / l;
    float* op = &g_ao[((size_t)(b * Nd + qi)) * Cd + h * HDd];
    #pragma unroll
    for (int d = 0; d < HDd; d += 4) {
        float4 t;
        t.x = acc[d] * inv; t.y = acc[d + 1] * inv;
        t.z = acc[d + 2] * inv; t.w = acc[d + 3] * inv;
        *(float4*)&op[d] = t;
    }
}

// ---------------- k mean over heads ----------------------------------------
__global__ __launch_bounds__(256)
void kmean_kernel(float* __restrict__ out)
{
    const int idx = blockIdx.x * 256 + threadIdx.x;   // over B*N*HD
    if (idx >= Bd * Nd * HDd) return;
    const int hd = idx & 63;
    const int n  = (idx >> 6) & 2047;
    const int b  = idx >> 17;
    float s = 0.f;
    #pragma unroll
    for (int h = 0; h < Hd; h++)
        s += g_k[(((size_t)(b * Hd + h)) * Nd + n) * HDd + hd];
    out[idx] = s * (1.0f / Hd);
}

// ---------------- launch ----------------------------------------------------
extern "C" void kernel_launch(void* const* d_in, const int* in_sizes, int n_in,
                              void* d_out, int out_size)
{
    const float* x    = (const float*)d_in[0];
    const float* size = (const float*)d_in[1];
    const float* q_w  = (const float*)d_in[2];
    const float* q_b  = (const float*)d_in[3];
    const float* k_w  = (const float*)d_in[4];
    const float* k_b  = (const float*)d_in[5];
    const float* v_w  = (const float*)d_in[6];
    const float* v_b  = (const float*)d_in[7];
    const float* o_w  = (const float*)d_in[8];
    const float* o_b  = (const float*)d_in[9];

    float* out   = (float*)d_out;                       // [B,N,C]
    float* kmean = out + (size_t)Bd * Nd * Cd;          // [B,N,HD]

    // 1) fused q/k/v projections
    dim3 gqkv(Cd / TN, (Bd * Nd) / TM, 3);
    gemm_qkv_kernel<<<gqkv, 256>>>(x, q_w, k_w, v_w, q_b, k_b, v_b);

    // 2) k mean over heads
    kmean_kernel<<<(Bd * Nd * HDd + 255) / 256, 256>>>(kmean);

    // 3) attention
    dim3 gat(Bd * Hd, Nd / AT_ROWS);
    attn_kernel<<<gat, AT_ROWS>>>(size);

    // 4) output projection
    dim3 go(Cd / TN, (Bd * Nd) / TM, 1);
    gemm_o_kernel<<<go, 256>>>(o_w, o_b, out);
}

// round 2
// speedup vs baseline: 3.9046x; 3.9046x over previous
#include <cuda_runtime.h>
#include <math.h>

#define Bd 8
#define Nd 2048
#define Cd 768
#define Hd 12
#define HDd 64
#define SCALEf 0.125f

// ---------------- scratch ----------------
__device__ float g_q[Bd * Hd * Nd * HDd];
__device__ float g_k[Bd * Hd * Nd * HDd];
__device__ float g_v[Bd * Hd * Nd * HDd];
__device__ float g_ao[Bd * Nd * Cd];

// ---------------- helpers ----------------
__device__ __forceinline__ unsigned f2tf(float f) {
    unsigned u;
    asm("cvt.rna.tf32.f32 %0, %1;" : "=r"(u) : "f"(f));
    return u;
}

__device__ __forceinline__ void mma8(float* c,
                                     unsigned a0, unsigned a1, unsigned a2, unsigned a3,
                                     unsigned b0, unsigned b1) {
    asm volatile(
        "mma.sync.aligned.m16n8k8.row.col.f32.tf32.tf32.f32 "
        "{%0,%1,%2,%3}, {%4,%5,%6,%7}, {%8,%9}, {%0,%1,%2,%3};"
        : "+f"(c[0]), "+f"(c[1]), "+f"(c[2]), "+f"(c[3])
        : "r"(a0), "r"(a1), "r"(a2), "r"(a3), "r"(b0), "r"(b1));
}

// ================= tf32 GEMM: y[m,d] = sum_c A[m,c] * W[d,c] + bias[d] =====
// BM=128, BN=128, BK=16; 256 threads = 8 warps (2x4); warp tile 64x32.
#define GSTR 20   // padded smem row stride (floats): conflict-free & 16B aligned

__global__ __launch_bounds__(256)
void gemm_qkv_tf32(const float* __restrict__ x,
                   const float* __restrict__ wq, const float* __restrict__ wk,
                   const float* __restrict__ wv,
                   const float* __restrict__ bq, const float* __restrict__ bk,
                   const float* __restrict__ bv)
{
    __shared__ float As[128 * GSTR];
    __shared__ float Bs[128 * GSTR];

    const int z = blockIdx.z;
    const float* W    = (z == 0) ? wq : (z == 1) ? wk : wv;
    const float* bias = (z == 0) ? bq : (z == 1) ? bk : bv;
    float* outp       = (z == 0) ? g_q : (z == 1) ? g_k : g_v;

    const int m0 = blockIdx.y * 128, n0 = blockIdx.x * 128;
    const int tid = threadIdx.x, lane = tid & 31, warp = tid >> 5;
    const int wm = warp >> 2, wn = warp & 3;
    const int gid = lane >> 2, tig = lane & 3;

    const int r0l = tid >> 2;          // rows 0..63
    const int r1l = r0l + 64;          // rows 64..127
    const int c0l = (tid & 3) << 2;    // col 0,4,8,12

    const float* Ap = x + (size_t)m0 * Cd;
    const float* Wp = W + (size_t)n0 * Cd;

    float4 ra0 = *(const float4*)(Ap + (size_t)r0l * Cd + c0l);
    float4 ra1 = *(const float4*)(Ap + (size_t)r1l * Cd + c0l);
    float4 rb0 = *(const float4*)(Wp + (size_t)r0l * Cd + c0l);
    float4 rb1 = *(const float4*)(Wp + (size_t)r1l * Cd + c0l);

    float acc[4][4][4];
    #pragma unroll
    for (int i = 0; i < 4; i++)
        #pragma unroll
        for (int j = 0; j < 4; j++)
            #pragma unroll
            for (int r = 0; r < 4; r++) acc[i][j][r] = 0.f;

    for (int k0 = 0; k0 < Cd; k0 += 16) {
        uint4 u;
        u = make_uint4(f2tf(ra0.x), f2tf(ra0.y), f2tf(ra0.z), f2tf(ra0.w));
        *(uint4*)&As[r0l * GSTR + c0l] = u;
        u = make_uint4(f2tf(ra1.x), f2tf(ra1.y), f2tf(ra1.z), f2tf(ra1.w));
        *(uint4*)&As[r1l * GSTR + c0l] = u;
        u = make_uint4(f2tf(rb0.x), f2tf(rb0.y), f2tf(rb0.z), f2tf(rb0.w));
        *(uint4*)&Bs[r0l * GSTR + c0l] = u;
        u = make_uint4(f2tf(rb1.x), f2tf(rb1.y), f2tf(rb1.z), f2tf(rb1.w));
        *(uint4*)&Bs[r1l * GSTR + c0l] = u;
        __syncthreads();

        if (k0 + 16 < Cd) {
            ra0 = *(const float4*)(Ap + (size_t)r0l * Cd + k0 + 16 + c0l);
            ra1 = *(const float4*)(Ap + (size_t)r1l * Cd + k0 + 16 + c0l);
            rb0 = *(const float4*)(Wp + (size_t)r0l * Cd + k0 + 16 + c0l);
            rb1 = *(const float4*)(Wp + (size_t)r1l * Cd + k0 + 16 + c0l);
        }

        #pragma unroll
        for (int ks = 0; ks < 2; ks++) {
            const int kk = ks * 8;
            unsigned a[4][4], bf[4][2];
            #pragma unroll
            for (int mi = 0; mi < 4; mi++) {
                const int r = wm * 64 + mi * 16 + gid;
                a[mi][0] = __float_as_uint(As[r * GSTR + kk + tig]);
                a[mi][1] = __float_as_uint(As[(r + 8) * GSTR + kk + tig]);
                a[mi][2] = __float_as_uint(As[r * GSTR + kk + tig + 4]);
                a[mi][3] = __float_as_uint(As[(r + 8) * GSTR + kk + tig + 4]);
            }
            #pragma unroll
            for (int ni = 0; ni < 4; ni++) {
                const int c = wn * 32 + ni * 8 + gid;
                bf[ni][0] = __float_as_uint(Bs[c * GSTR + kk + tig]);
                bf[ni][1] = __float_as_uint(Bs[c * GSTR + kk + tig + 4]);
            }
            #pragma unroll
            for (int mi = 0; mi < 4; mi++)
                #pragma unroll
                for (int ni = 0; ni < 4; ni++)
                    mma8(acc[mi][ni], a[mi][0], a[mi][1], a[mi][2], a[mi][3],
                         bf[ni][0], bf[ni][1]);
        }
        __syncthreads();
    }

    // epilogue: scatter to [B,H,N,HD], rounded to tf32 for downstream mma
    #pragma unroll
    for (int mi = 0; mi < 4; mi++) {
        #pragma unroll
        for (int ni = 0; ni < 4; ni++) {
            const int row = m0 + wm * 64 + mi * 16 + gid;
            const int col = n0 + wn * 32 + ni * 8 + 2 * tig;
            const float b0v = bias[col], b1v = bias[col + 1];
            const int h = col >> 6, hd = col & 63;
            #pragma unroll
            for (int hh = 0; hh < 2; hh++) {
                const int r = row + hh * 8;
                const int bb = r >> 11, n = r & 2047;
                float2 v;
                v.x = __uint_as_float(f2tf(acc[mi][ni][hh * 2 + 0] + b0v));
                v.y = __uint_as_float(f2tf(acc[mi][ni][hh * 2 + 1] + b1v));
                *(float2*)&outp[(((size_t)(bb * Hd + h)) * Nd + n) * HDd + hd] = v;
            }
        }
    }
}

__global__ __launch_bounds__(256)
void gemm_o_tf32(const float* __restrict__ W,
                 const float* __restrict__ bias,
                 float* __restrict__ out)
{
    __shared__ float As[128 * GSTR];
    __shared__ float Bs[128 * GSTR];

    const int m0 = blockIdx.y * 128, n0 = blockIdx.x * 128;
    const int tid = threadIdx.x, lane = tid & 31, warp = tid >> 5;
    const int wm = warp >> 2, wn = warp & 3;
    const int gid = lane >> 2, tig = lane & 3;

    const int r0l = tid >> 2;
    const int r1l = r0l + 64;
    const int c0l = (tid & 3) << 2;

    const float* Ap = g_ao + (size_t)m0 * Cd;
    const float* Wp = W + (size_t)n0 * Cd;

    float4 ra0 = *(const float4*)(Ap + (size_t)r0l * Cd + c0l);
    float4 ra1 = *(const float4*)(Ap + (size_t)r1l * Cd + c0l);
    float4 rb0 = *(const float4*)(Wp + (size_t)r0l * Cd + c0l);
    float4 rb1 = *(const float4*)(Wp + (size_t)r1l * Cd + c0l);

    float acc[4][4][4];
    #pragma unroll
    for (int i = 0; i < 4; i++)
        #pragma unroll
        for (int j = 0; j < 4; j++)
            #pragma unroll
            for (int r = 0; r < 4; r++) acc[i][j][r] = 0.f;

    for (int k0 = 0; k0 < Cd; k0 += 16) {
        uint4 u;
        u = make_uint4(f2tf(ra0.x), f2tf(ra0.y), f2tf(ra0.z), f2tf(ra0.w));
        *(uint4*)&As[r0l * GSTR + c0l] = u;
        u = make_uint4(f2tf(ra1.x), f2tf(ra1.y), f2tf(ra1.z), f2tf(ra1.w));
        *(uint4*)&As[r1l * GSTR + c0l] = u;
        u = make_uint4(f2tf(rb0.x), f2tf(rb0.y), f2tf(rb0.z), f2tf(rb0.w));
        *(uint4*)&Bs[r0l * GSTR + c0l] = u;
        u = make_uint4(f2tf(rb1.x), f2tf(rb1.y), f2tf(rb1.z), f2tf(rb1.w));
        *(uint4*)&Bs[r1l * GSTR + c0l] = u;
        __syncthreads();

        if (k0 + 16 < Cd) {
            ra0 = *(const float4*)(Ap + (size_t)r0l * Cd + k0 + 16 + c0l);
            ra1 = *(const float4*)(Ap + (size_t)r1l * Cd + k0 + 16 + c0l);
            rb0 = *(const float4*)(Wp + (size_t)r0l * Cd + k0 + 16 + c0l);
            rb1 = *(const float4*)(Wp + (size_t)r1l * Cd + k0 + 16 + c0l);
        }

        #pragma unroll
        for (int ks = 0; ks < 2; ks++) {
            const int kk = ks * 8;
            unsigned a[4][4], bf[4][2];
            #pragma unroll
            for (int mi = 0; mi < 4; mi++) {
                const int r = wm * 64 + mi * 16 + gid;
                a[mi][0] = __float_as_uint(As[r * GSTR + kk + tig]);
                a[mi][1] = __float_as_uint(As[(r + 8) * GSTR + kk + tig]);
                a[mi][2] = __float_as_uint(As[r * GSTR + kk + tig + 4]);
                a[mi][3] = __float_as_uint(As[(r + 8) * GSTR + kk + tig + 4]);
            }
            #pragma unroll
            for (int ni = 0; ni < 4; ni++) {
                const int c = wn * 32 + ni * 8 + gid;
                bf[ni][0] = __float_as_uint(Bs[c * GSTR + kk + tig]);
                bf[ni][1] = __float_as_uint(Bs[c * GSTR + kk + tig + 4]);
            }
            #pragma unroll
            for (int mi = 0; mi < 4; mi++)
                #pragma unroll
                for (int ni = 0; ni < 4; ni++)
                    mma8(acc[mi][ni], a[mi][0], a[mi][1], a[mi][2], a[mi][3],
                         bf[ni][0], bf[ni][1]);
        }
        __syncthreads();
    }

    #pragma unroll
    for (int mi = 0; mi < 4; mi++) {
        #pragma unroll
        for (int ni = 0; ni < 4; ni++) {
            const int row = m0 + wm * 64 + mi * 16 + gid;
            const int col = n0 + wn * 32 + ni * 8 + 2 * tig;
            const float b0v = bias[col], b1v = bias[col + 1];
            #pragma unroll
            for (int hh = 0; hh < 2; hh++) {
                const int r = row + hh * 8;
                float2 v;
                v.x = acc[mi][ni][hh * 2 + 0] + b0v;
                v.y = acc[mi][ni][hh * 2 + 1] + b1v;
                *(float2*)&out[(size_t)r * Cd + col] = v;
            }
        }
    }
}

// ================= attention (tf32 mma) ====================================
// block: 256 threads (8 warps, 4x2), 128 q-rows, 64-key chunks.
// smem float offsets (strides padded for conflict-free fragment LDS)
#define SQ 0
#define SK (SQ + 128 * 68)
#define SV (SK + 64 * 68)
#define SP (SV + 64 * 72)
#define SS (SP + 128 * 68)
#define SL (SS + 64)
#define SMF (SL + 256)          // 26688 floats = 106752 bytes

__global__ __launch_bounds__(256)
void attn_tf32(const float* __restrict__ size)
{
    extern __shared__ float sm[];

    const int bh = blockIdx.x;
    const int b = bh / Hd, h = bh % Hd;
    const int q0 = blockIdx.y * 128;
    const int tid = threadIdx.x, lane = tid & 31, warp = tid >> 5;
    const int wm = warp >> 1;     // 0..3 : q rows wm*32
    const int wn = warp & 1;      // 0..1 : key/d cols wn*32
    const int gid = lane >> 2, tig = lane & 3;

    // load Q tile (already tf32-rounded)
    const float* qbase = g_q + ((size_t)bh * Nd + q0) * HDd;
    #pragma unroll
    for (int i = 0; i < 8; i++) {
        const int f = tid + i * 256;
        const int row = f >> 4, c4 = (f & 15) << 2;
        *(float4*)&sm[SQ + row * 68 + c4] = *(const float4*)(qbase + row * HDd + c4);
    }

    const float* kbase = g_k + (size_t)bh * Nd * HDd;
    const float* vbase = g_v + (size_t)bh * Nd * HDd;
    const float* sbase = size + (size_t)b * Nd;

    float acc[2][4][4];
    #pragma unroll
    for (int i = 0; i < 2; i++)
        #pragma unroll
        for (int j = 0; j < 4; j++)
            #pragma unroll
            for (int r = 0; r < 4; r++) acc[i][j][r] = 0.f;
    float lsum[2][2] = {{0.f, 0.f}, {0.f, 0.f}};

    for (int kc = 0; kc < Nd; kc += 64) {
        __syncthreads();
        #pragma unroll
        for (int i = 0; i < 4; i++) {
            const int f = tid + i * 256;
            const int row = f >> 4, c4 = (f & 15) << 2;
            *(float4*)&sm[SK + row * 68 + c4] = *(const float4*)(kbase + (kc + row) * HDd + c4);
            *(float4*)&sm[SV + row * 72 + c4] = *(const float4*)(vbase + (kc + row) * HDd + c4);
        }
        if (tid < 64) sm[SS + tid] = sbase[kc + tid];
        __syncthreads();

        // ---- S = Q @ K^T (warp: 32q x 32key) ----
        float sc[2][4][4];
        #pragma unroll
        for (int i = 0; i < 2; i++)
            #pragma unroll
            for (int j = 0; j < 4; j++)
                #pragma unroll
                for (int r = 0; r < 4; r++) sc[i][j][r] = 0.f;

        #pragma unroll
        for (int ks = 0; ks < 8; ks++) {
            const int kk = ks * 8;
            unsigned a[2][4], bf[4][2];
            #pragma unroll
            for (int mi = 0; mi < 2; mi++) {
                const int r = wm * 32 + mi * 16 + gid;
                a[mi][0] = __float_as_uint(sm[SQ + r * 68 + kk + tig]);
                a[mi][1] = __float_as_uint(sm[SQ + (r + 8) * 68 + kk + tig]);
                a[mi][2] = __float_as_uint(sm[SQ + r * 68 + kk + tig + 4]);
                a[mi][3] = __float_as_uint(sm[SQ + (r + 8) * 68 + kk + tig + 4]);
            }
            #pragma unroll
            for (int ni = 0; ni < 4; ni++) {
                const int c = wn * 32 + ni * 8 + gid;
                bf[ni][0] = __float_as_uint(sm[SK + c * 68 + kk + tig]);
                bf[ni][1] = __float_as_uint(sm[SK + c * 68 + kk + tig + 4]);
            }
            #pragma unroll
            for (int mi = 0; mi < 2; mi++)
                #pragma unroll
                for (int ni = 0; ni < 4; ni++)
                    mma8(sc[mi][ni], a[mi][0], a[mi][1], a[mi][2], a[mi][3],
                         bf[ni][0], bf[ni][1]);
        }

        // ---- p = size_k * exp(s*scale); store tf32 P; accumulate l ----
        #pragma unroll
        for (int mi = 0; mi < 2; mi++) {
            #pragma unroll
            for (int ni = 0; ni < 4; ni++) {
                const int row = wm * 32 + mi * 16 + gid;
                const int col = wn * 32 + ni * 8 + 2 * tig;
                const float sz0 = sm[SS + col], sz1 = sm[SS + col + 1];
                float p0 = sz0 * __expf(sc[mi][ni][0] * SCALEf);
                float p1 = sz1 * __expf(sc[mi][ni][1] * SCALEf);
                float p2 = sz0 * __expf(sc[mi][ni][2] * SCALEf);
                float p3 = sz1 * __expf(sc[mi][ni][3] * SCALEf);
                lsum[mi][0] += p0 + p1;
                lsum[mi][1] += p2 + p3;
                float2 v;
                v.x = __uint_as_float(f2tf(p0));
                v.y = __uint_as_float(f2tf(p1));
                *(float2*)&sm[SP + row * 68 + col] = v;
                v.x = __uint_as_float(f2tf(p2));
                v.y = __uint_as_float(f2tf(p3));
                *(float2*)&sm[SP + (row + 8) * 68 + col] = v;
            }
        }
        __syncthreads();

        // ---- O += P @ V (warp: 32q x 32d) ----
        #pragma unroll
        for (int ks = 0; ks < 8; ks++) {
            const int kk = ks * 8;
            unsigned a[2][4], bf[4][2];
            #pragma unroll
            for (int mi = 0; mi < 2; mi++) {
                const int r = wm * 32 + mi * 16 + gid;
                a[mi][0] = __float_as_uint(sm[SP + r * 68 + kk + tig]);
                a[mi][1] = __float_as_uint(sm[SP + (r + 8) * 68 + kk + tig]);
                a[mi][2] = __float_as_uint(sm[SP + r * 68 + kk + tig + 4]);
                a[mi][3] = __float_as_uint(sm[SP + (r + 8) * 68 + kk + tig + 4]);
            }
            #pragma unroll
            for (int ni = 0; ni < 4; ni++) {
                const int d = wn * 32 + ni * 8 + gid;
                bf[ni][0] = __float_as_uint(sm[SV + (kk + tig) * 72 + d]);
                bf[ni][1] = __float_as_uint(sm[SV + (kk + tig + 4) * 72 + d]);
            }
            #pragma unroll
            for (int mi = 0; mi < 2; mi++)
                #pragma unroll
                for (int ni = 0; ni < 4; ni++)
                    mma8(acc[mi][ni], a[mi][0], a[mi][1], a[mi][2], a[mi][3],
                         bf[ni][0], bf[ni][1]);
        }
    }

    // ---- reduce l across lane quads and the 2 key-partition warps ----
    #pragma unroll
    for (int mi = 0; mi < 2; mi++) {
        #pragma unroll
        for (int hh = 0; hh < 2; hh++) {
            float v = lsum[mi][hh];
            v += __shfl_xor_sync(0xFFFFFFFFu, v, 1);
            v += __shfl_xor_sync(0xFFFFFFFFu, v, 2);
            if (tig == 0)
                sm[SL + wn * 128 + wm * 32 + mi * 16 + hh * 8 + gid] = v;
        }
    }
    __syncthreads();

    // ---- normalize and write out ----
    #pragma unroll
    for (int mi = 0; mi < 2; mi++) {
        #pragma unroll
        for (int ni = 0; ni < 4; ni++) {
            const int rowl = wm * 32 + mi * 16 + gid;
            const int col = wn * 32 + ni * 8 + 2 * tig;
            #pragma unroll
            for (int hh = 0; hh < 2; hh++) {
                const int r = rowl + hh * 8;
                const float linv = 1.f / (sm[SL + r] + sm[SL + 128 + r]);
                float2 v;
                v.x = acc[mi][ni][hh * 2 + 0] * linv;
                v.y = acc[mi][ni][hh * 2 + 1] * linv;
                *(float2*)&g_ao[((size_t)(b * Nd + q0 + r)) * Cd + h * HDd + col] = v;
            }
        }
    }
}

// ---------------- k mean over heads ----------------------------------------
__global__ __launch_bounds__(256)
void kmean_kernel(float* __restrict__ out)
{
    const int idx = blockIdx.x * 256 + threadIdx.x;
    if (idx >= Bd * Nd * HDd) return;
    const int hd = idx & 63;
    const int n  = (idx >> 6) & 2047;
    const int b  = idx >> 17;
    float s = 0.f;
    #pragma unroll
    for (int h = 0; h < Hd; h++)
        s += g_k[(((size_t)(b * Hd + h)) * Nd + n) * HDd + hd];
    out[idx] = s * (1.0f / Hd);
}

// ---------------- launch ----------------------------------------------------
extern "C" void kernel_launch(void* const* d_in, const int* in_sizes, int n_in,
                              void* d_out, int out_size)
{
    const float* x    = (const float*)d_in[0];
    const float* size = (const float*)d_in[1];
    const float* q_w  = (const float*)d_in[2];
    const float* q_b  = (const float*)d_in[3];
    const float* k_w  = (const float*)d_in[4];
    const float* k_b  = (const float*)d_in[5];
    const float* v_w  = (const float*)d_in[6];
    const float* v_b  = (const float*)d_in[7];
    const float* o_w  = (const float*)d_in[8];
    const float* o_b  = (const float*)d_in[9];

    float* out   = (float*)d_out;
    float* kmean = out + (size_t)Bd * Nd * Cd;

    cudaFuncSetAttribute(attn_tf32, cudaFuncAttributeMaxDynamicSharedMemorySize,
                         SMF * 4);

    dim3 gqkv(Cd / 128, (Bd * Nd) / 128, 3);
    gemm_qkv_tf32<<<gqkv, 256>>>(x, q_w, k_w, v_w, q_b, k_b, v_b);

    kmean_kernel<<<(Bd * Nd * HDd + 255) / 256, 256>>>(kmean);

    dim3 gat(Bd * Hd, Nd / 128);
    attn_tf32<<<gat, 256, SMF * 4>>>(size);

    dim3 go(Cd / 128, (Bd * Nd) / 128, 1);
    gemm_o_tf32<<<go, 256>>>(o_w, o_b, out);
}

// round 5
// speedup vs baseline: 4.8241x; 1.2355x over previous
#include <cuda_runtime.h>
#include <cuda_fp16.h>
#include <math.h>
#include <cstdint>

#define Bd 8
#define Nd 2048
#define Cd 768
#define Hd 12
#define HDd 64
#define SCALEf 0.125f

// ---------------- scratch ----------------
__device__ float g_k[Bd * Hd * Nd * HDd];      // fp32 k (for kmean)
__device__ __half g_qh[Bd * Hd * Nd * HDd];    // fp16, pre-scaled by 0.125
__device__ __half g_kh[Bd * Hd * Nd * HDd];
__device__ __half g_vh[Bd * Hd * Nd * HDd];
__device__ float g_ao[Bd * Nd * Cd];

// ---------------- helpers ----------------
__device__ __forceinline__ unsigned f2tf(float f) {
    unsigned u;
    asm("cvt.rna.tf32.f32 %0, %1;" : "=r"(u) : "f"(f));
    return u;
}

__device__ __forceinline__ uint32_t smem_u32(const void* p) {
    uint32_t a;
    asm("{ .reg .u64 t; cvta.to.shared.u64 t, %1; cvt.u32.u64 %0, t; }"
        : "=r"(a) : "l"(p));
    return a;
}

__device__ __forceinline__ void mma8(float* c,
                                     unsigned a0, unsigned a1, unsigned a2, unsigned a3,
                                     unsigned b0, unsigned b1) {
    asm volatile(
        "mma.sync.aligned.m16n8k8.row.col.f32.tf32.tf32.f32 "
        "{%0,%1,%2,%3}, {%4,%5,%6,%7}, {%8,%9}, {%0,%1,%2,%3};"
        : "+f"(c[0]), "+f"(c[1]), "+f"(c[2]), "+f"(c[3])
        : "r"(a0), "r"(a1), "r"(a2), "r"(a3), "r"(b0), "r"(b1));
}

__device__ __forceinline__ void mmah(float* c,
                                     unsigned a0, unsigned a1, unsigned a2, unsigned a3,
                                     unsigned b0, unsigned b1) {
    asm volatile(
        "mma.sync.aligned.m16n8k16.row.col.f32.f16.f16.f32 "
        "{%0,%1,%2,%3}, {%4,%5,%6,%7}, {%8,%9}, {%0,%1,%2,%3};"
        : "+f"(c[0]), "+f"(c[1]), "+f"(c[2]), "+f"(c[3])
        : "r"(a0), "r"(a1), "r"(a2), "r"(a3), "r"(b0), "r"(b1));
}

#define LDM_X4(r0, r1, r2, r3, addr) \
    asm volatile("ldmatrix.sync.aligned.m8n8.x4.shared.b16 {%0,%1,%2,%3}, [%4];" \
                 : "=r"(r0), "=r"(r1), "=r"(r2), "=r"(r3) : "r"(addr))

#define LDM_X4T(r0, r1, r2, r3, addr) \
    asm volatile("ldmatrix.sync.aligned.m8n8.x4.trans.shared.b16 {%0,%1,%2,%3}, [%4];" \
                 : "=r"(r0), "=r"(r1), "=r"(r2), "=r"(r3) : "r"(addr))

#define SWZ(x) ((x) ^ (((x) >> 3) & 0x70))

__device__ __forceinline__ uint32_t packh(float a, float b) {
    __half2 t = __floats2half2_rn(a, b);
    return *reinterpret_cast<uint32_t*>(&t);
}

// ================= tf32 GEMM (R2-proven) ===================================
#define GSTR 20

__global__ __launch_bounds__(256)
void gemm_qkv_tf32(const float* __restrict__ x,
                   const float* __restrict__ wq, const float* __restrict__ wk,
                   const float* __restrict__ wv,
                   const float* __restrict__ bq, const float* __restrict__ bk,
                   const float* __restrict__ bv)
{
    __shared__ float As[128 * GSTR];
    __shared__ float Bs[128 * GSTR];

    const int z = blockIdx.z;
    const float* W    = (z == 0) ? wq : (z == 1) ? wk : wv;
    const float* bias = (z == 0) ? bq : (z == 1) ? bk : bv;
    __half* outb = (z == 0) ? g_qh : (z == 1) ? g_kh : g_vh;
    const float mult  = (z == 0) ? SCALEf : 1.0f;

    const int m0 = blockIdx.y * 128, n0 = blockIdx.x * 128;
    const int tid = threadIdx.x, lane = tid & 31, warp = tid >> 5;
    const int wm = warp >> 2, wn = warp & 3;
    const int gid = lane >> 2, tig = lane & 3;

    const int r0l = tid >> 2;
    const int r1l = r0l + 64;
    const int c0l = (tid & 3) << 2;

    const float* Ap = x + (size_t)m0 * Cd;
    const float* Wp = W + (size_t)n0 * Cd;

    float4 ra0 = *(const float4*)(Ap + (size_t)r0l * Cd + c0l);
    float4 ra1 = *(const float4*)(Ap + (size_t)r1l * Cd + c0l);
    float4 rb0 = *(const float4*)(Wp + (size_t)r0l * Cd + c0l);
    float4 rb1 = *(const float4*)(Wp + (size_t)r1l * Cd + c0l);

    float acc[4][4][4];
    #pragma unroll
    for (int i = 0; i < 4; i++)
        #pragma unroll
        for (int j = 0; j < 4; j++)
            #pragma unroll
            for (int r = 0; r < 4; r++) acc[i][j][r] = 0.f;

    for (int k0 = 0; k0 < Cd; k0 += 16) {
        uint4 u;
        u = make_uint4(f2tf(ra0.x), f2tf(ra0.y), f2tf(ra0.z), f2tf(ra0.w));
        *(uint4*)&As[r0l * GSTR + c0l] = u;
        u = make_uint4(f2tf(ra1.x), f2tf(ra1.y), f2tf(ra1.z), f2tf(ra1.w));
        *(uint4*)&As[r1l * GSTR + c0l] = u;
        u = make_uint4(f2tf(rb0.x), f2tf(rb0.y), f2tf(rb0.z), f2tf(rb0.w));
        *(uint4*)&Bs[r0l * GSTR + c0l] = u;
        u = make_uint4(f2tf(rb1.x), f2tf(rb1.y), f2tf(rb1.z), f2tf(rb1.w));
        *(uint4*)&Bs[r1l * GSTR + c0l] = u;
        __syncthreads();

        if (k0 + 16 < Cd) {
            ra0 = *(const float4*)(Ap + (size_t)r0l * Cd + k0 + 16 + c0l);
            ra1 = *(const float4*)(Ap + (size_t)r1l * Cd + k0 + 16 + c0l);
            rb0 = *(const float4*)(Wp + (size_t)r0l * Cd + k0 + 16 + c0l);
            rb1 = *(const float4*)(Wp + (size_t)r1l * Cd + k0 + 16 + c0l);
        }

        #pragma unroll
        for (int ks = 0; ks < 2; ks++) {
            const int kk = ks * 8;
            unsigned a[4][4], bf[4][2];
            #pragma unroll
            for (int mi = 0; mi < 4; mi++) {
                const int r = wm * 64 + mi * 16 + gid;
                a[mi][0] = __float_as_uint(As[r * GSTR + kk + tig]);
                a[mi][1] = __float_as_uint(As[(r + 8) * GSTR + kk + tig]);
                a[mi][2] = __float_as_uint(As[r * GSTR + kk + tig + 4]);
                a[mi][3] = __float_as_uint(As[(r + 8) * GSTR + kk + tig + 4]);
            }
            #pragma unroll
            for (int ni = 0; ni < 4; ni++) {
                const int c = wn * 32 + ni * 8 + gid;
                bf[ni][0] = __float_as_uint(Bs[c * GSTR + kk + tig]);
                bf[ni][1] = __float_as_uint(Bs[c * GSTR + kk + tig + 4]);
            }
            #pragma unroll
            for (int mi = 0; mi < 4; mi++)
                #pragma unroll
                for (int ni = 0; ni < 4; ni++)
                    mma8(acc[mi][ni], a[mi][0], a[mi][1], a[mi][2], a[mi][3],
                         bf[ni][0], bf[ni][1]);
        }
        __syncthreads();
    }

    // epilogue: scatter to [B,H,N,HD] as fp16 (q pre-scaled); k also fp32
    #pragma unroll
    for (int mi = 0; mi < 4; mi++) {
        #pragma unroll
        for (int ni = 0; ni < 4; ni++) {
            const int row = m0 + wm * 64 + mi * 16 + gid;
            const int col = n0 + wn * 32 + ni * 8 + 2 * tig;
            const float b0v = bias[col], b1v = bias[col + 1];
            const int h = col >> 6, hd = col & 63;
            #pragma unroll
            for (int hh = 0; hh < 2; hh++) {
                const int r = row + hh * 8;
                const int bb = r >> 11, n = r & 2047;
                const size_t idx = (((size_t)(bb * Hd + h)) * Nd + n) * HDd + hd;
                const float v0 = (acc[mi][ni][hh * 2 + 0] + b0v) * mult;
                const float v1 = (acc[mi][ni][hh * 2 + 1] + b1v) * mult;
                *(uint32_t*)&outb[idx] = packh(v0, v1);
                if (z == 1) *(float2*)&g_k[idx] = make_float2(v0, v1);
            }
        }
    }
}

__global__ __launch_bounds__(256)
void gemm_o_tf32(const float* __restrict__ W,
                 const float* __restrict__ bias,
                 float* __restrict__ out)
{
    __shared__ float As[128 * GSTR];
    __shared__ float Bs[128 * GSTR];

    const int m0 = blockIdx.y * 128, n0 = blockIdx.x * 128;
    const int tid = threadIdx.x, lane = tid & 31, warp = tid >> 5;
    const int wm = warp >> 2, wn = warp & 3;
    const int gid = lane >> 2, tig = lane & 3;

    const int r0l = tid >> 2;
    const int r1l = r0l + 64;
    const int c0l = (tid & 3) << 2;

    const float* Ap = g_ao + (size_t)m0 * Cd;
    const float* Wp = W + (size_t)n0 * Cd;

    float4 ra0 = *(const float4*)(Ap + (size_t)r0l * Cd + c0l);
    float4 ra1 = *(const float4*)(Ap + (size_t)r1l * Cd + c0l);
    float4 rb0 = *(const float4*)(Wp + (size_t)r0l * Cd + c0l);
    float4 rb1 = *(const float4*)(Wp + (size_t)r1l * Cd + c0l);

    float acc[4][4][4];
    #pragma unroll
    for (int i = 0; i < 4; i++)
        #pragma unroll
        for (int j = 0; j < 4; j++)
            #pragma unroll
            for (int r = 0; r < 4; r++) acc[i][j][r] = 0.f;

    for (int k0 = 0; k0 < Cd; k0 += 16) {
        uint4 u;
        u = make_uint4(f2tf(ra0.x), f2tf(ra0.y), f2tf(ra0.z), f2tf(ra0.w));
        *(uint4*)&As[r0l * GSTR + c0l] = u;
        u = make_uint4(f2tf(ra1.x), f2tf(ra1.y), f2tf(ra1.z), f2tf(ra1.w));
        *(uint4*)&As[r1l * GSTR + c0l] = u;
        u = make_uint4(f2tf(rb0.x), f2tf(rb0.y), f2tf(rb0.z), f2tf(rb0.w));
        *(uint4*)&Bs[r0l * GSTR + c0l] = u;
        u = make_uint4(f2tf(rb1.x), f2tf(rb1.y), f2tf(rb1.z), f2tf(rb1.w));
        *(uint4*)&Bs[r1l * GSTR + c0l] = u;
        __syncthreads();

        if (k0 + 16 < Cd) {
            ra0 = *(const float4*)(Ap + (size_t)r0l * Cd + k0 + 16 + c0l);
            ra1 = *(const float4*)(Ap + (size_t)r1l * Cd + k0 + 16 + c0l);
            rb0 = *(const float4*)(Wp + (size_t)r0l * Cd + k0 + 16 + c0l);
            rb1 = *(const float4*)(Wp + (size_t)r1l * Cd + k0 + 16 + c0l);
        }

        #pragma unroll
        for (int ks = 0; ks < 2; ks++) {
            const int kk = ks * 8;
            unsigned a[4][4], bf[4][2];
            #pragma unroll
            for (int mi = 0; mi < 4; mi++) {
                const int r = wm * 64 + mi * 16 + gid;
                a[mi][0] = __float_as_uint(As[r * GSTR + kk + tig]);
                a[mi][1] = __float_as_uint(As[(r + 8) * GSTR + kk + tig]);
                a[mi][2] = __float_as_uint(As[r * GSTR + kk + tig + 4]);
                a[mi][3] = __float_as_uint(As[(r + 8) * GSTR + kk + tig + 4]);
            }
            #pragma unroll
            for (int ni = 0; ni < 4; ni++) {
                const int c = wn * 32 + ni * 8 + gid;
                bf[ni][0] = __float_as_uint(Bs[c * GSTR + kk + tig]);
                bf[ni][1] = __float_as_uint(Bs[c * GSTR + kk + tig + 4]);
            }
            #pragma unroll
            for (int mi = 0; mi < 4; mi++)
                #pragma unroll
                for (int ni = 0; ni < 4; ni++)
                    mma8(acc[mi][ni], a[mi][0], a[mi][1], a[mi][2], a[mi][3],
                         bf[ni][0], bf[ni][1]);
        }
        __syncthreads();
    }

    #pragma unroll
    for (int mi = 0; mi < 4; mi++) {
        #pragma unroll
        for (int ni = 0; ni < 4; ni++) {
            const int row = m0 + wm * 64 + mi * 16 + gid;
            const int col = n0 + wn * 32 + ni * 8 + 2 * tig;
            const float b0v = bias[col], b1v = bias[col + 1];
            #pragma unroll
            for (int hh = 0; hh < 2; hh++) {
                const int r = row + hh * 8;
                float2 v;
                v.x = acc[mi][ni][hh * 2 + 0] + b0v;
                v.y = acc[mi][ni][hh * 2 + 1] + b1v;
                *(float2*)&out[(size_t)r * Cd + col] = v;
            }
        }
    }
}

// ================= attention: fp16 mma + ldmatrix ==========================
// smem byte offsets (all tiles: 128B rows, SW128 swizzled)
#define QS 0
#define KS 16384
#define VS 24576
#define PS 32768
#define SZB 49152
#define SLB 49408
#define ASM_TOTAL 50432

__global__ __launch_bounds__(256)
void attn_fp16(const float* __restrict__ size)
{
    extern __shared__ char smc[];
    const uint32_t sb = smem_u32(smc);

    const int bh = blockIdx.x;
    const int b = bh / Hd, h = bh % Hd;
    const int q0 = blockIdx.y * 128;
    const int tid = threadIdx.x, lane = tid & 31, warp = tid >> 5;
    const int wm = warp >> 1;       // q block 32 rows
    const int wn = warp & 1;        // key/d block 32 cols
    const int gid = lane >> 2, tig = lane & 3;

    // --- load Q tile: 128 rows x 128B, fp16, pre-scaled ---
    const char* qb = (const char*)(g_qh + ((size_t)bh * Nd + q0) * HDd);
    #pragma unroll
    for (int i = 0; i < 4; i++) {
        const int f = tid + i * 256;
        const int row = f >> 3, seg = (f & 7) * 16;
        *(uint4*)(smc + QS + SWZ(row * 128 + seg)) =
            *(const uint4*)(qb + (size_t)row * 128 + seg);
    }

    const char* kbb = (const char*)(g_kh + (size_t)bh * Nd * HDd);
    const char* vbb = (const char*)(g_vh + (size_t)bh * Nd * HDd);
    const float* sbase = size + (size_t)b * Nd;

    float acc[2][4][4];
    #pragma unroll
    for (int i = 0; i < 2; i++)
        #pragma unroll
        for (int j = 0; j < 4; j++)
            #pragma unroll
            for (int r = 0; r < 4; r++) acc[i][j][r] = 0.f;
    float lsum[2][2] = {{0.f, 0.f}, {0.f, 0.f}};

    // ldmatrix lane addressing pieces (constant per thread)
    const int a_row = (lane & 15);
    const int a_bc  = (lane >> 4) << 4;
    const int b_row = (lane & 7) + ((lane >> 4) << 3);
    const int b_bc  = ((lane >> 3) & 1) << 4;
    const int v_row = (lane & 7) + (((lane >> 3) & 1) << 3);
    const int v_bc  = (lane >> 4) << 4;

    for (int kc = 0; kc < Nd; kc += 64) {
        __syncthreads();
        // --- load K,V tiles: 64 rows x 128B each ---
        #pragma unroll
        for (int i = 0; i < 2; i++) {
            const int f = tid + i * 256;
            const int row = f >> 3, seg = (f & 7) * 16;
            *(uint4*)(smc + KS + SWZ(row * 128 + seg)) =
                *(const uint4*)(kbb + ((size_t)(kc + row)) * 128 + seg);
            *(uint4*)(smc + VS + SWZ(row * 128 + seg)) =
                *(const uint4*)(vbb + ((size_t)(kc + row)) * 128 + seg);
        }
        if (tid < 64) *(float*)(smc + SZB + tid * 4) = sbase[kc + tid];
        __syncthreads();

        // ---- S = Q @ K^T ----
        float sc[2][4][4];
        #pragma unroll
        for (int i = 0; i < 2; i++)
            #pragma unroll
            for (int j = 0; j < 4; j++)
                #pragma unroll
                for (int r = 0; r < 4; r++) sc[i][j][r] = 0.f;

        #pragma unroll
        for (int ks = 0; ks < 4; ks++) {
            uint32_t a[2][4], bk[2][4];
            #pragma unroll
            for (int mi = 0; mi < 2; mi++) {
                const int row = wm * 32 + mi * 16 + a_row;
                LDM_X4(a[mi][0], a[mi][1], a[mi][2], a[mi][3],
                       sb + QS + SWZ(row * 128 + ks * 32 + a_bc));
            }
            #pragma unroll
            for (int nh = 0; nh < 2; nh++) {
                const int row = wn * 32 + nh * 16 + b_row;
                LDM_X4(bk[nh][0], bk[nh][1], bk[nh][2], bk[nh][3],
                       sb + KS + SWZ(row * 128 + ks * 32 + b_bc));
            }
            #pragma unroll
            for (int mi = 0; mi < 2; mi++)
                #pragma unroll
                for (int ni = 0; ni < 4; ni++)
                    mmah(sc[mi][ni], a[mi][0], a[mi][1], a[mi][2], a[mi][3],
                         bk[ni >> 1][(ni & 1) * 2], bk[ni >> 1][(ni & 1) * 2 + 1]);
        }

        // ---- p = size_k * exp(s); store fp16 P; accumulate l ----
        #pragma unroll
        for (int mi = 0; mi < 2; mi++) {
            #pragma unroll
            for (int ni = 0; ni < 4; ni++) {
                const int row = wm * 32 + mi * 16 + gid;
                const int col = wn * 32 + ni * 8 + 2 * tig;
                const float sz0 = *(const float*)(smc + SZB + col * 4);
                const float sz1 = *(const float*)(smc + SZB + col * 4 + 4);
                const float p0 = sz0 * __expf(sc[mi][ni][0]);
                const float p1 = sz1 * __expf(sc[mi][ni][1]);
                const float p2 = sz0 * __expf(sc[mi][ni][2]);
                const float p3 = sz1 * __expf(sc[mi][ni][3]);
                lsum[mi][0] += p0 + p1;
                lsum[mi][1] += p2 + p3;
                *(uint32_t*)(smc + PS + SWZ(row * 128 + col * 2)) = packh(p0, p1);
                *(uint32_t*)(smc + PS + SWZ((row + 8) * 128 + col * 2)) = packh(p2, p3);
            }
        }
        __syncthreads();

        // ---- O += P @ V ----
        #pragma unroll
        for (int ks = 0; ks < 4; ks++) {
            uint32_t a[2][4], bv[2][4];
            #pragma unroll
            for (int mi = 0; mi < 2; mi++) {
                const int row = wm * 32 + mi * 16 + a_row;
                LDM_X4(a[mi][0], a[mi][1], a[mi][2], a[mi][3],
                       sb + PS + SWZ(row * 128 + ks * 32 + a_bc));
            }
            #pragma unroll
            for (int dh = 0; dh < 2; dh++) {
                const int row = ks * 16 + v_row;
                const int bcol = (wn * 32 + dh * 16) * 2 + v_bc;
                LDM_X4T(bv[dh][0], bv[dh][1], bv[dh][2], bv[dh][3],
                        sb + VS + SWZ(row * 128 + bcol));
            }
            #pragma unroll
            for (int mi = 0; mi < 2; mi++)
                #pragma unroll
                for (int ni = 0; ni < 4; ni++)
                    mmah(acc[mi][ni], a[mi][0], a[mi][1], a[mi][2], a[mi][3],
                         bv[ni >> 1][(ni & 1) * 2], bv[ni >> 1][(ni & 1) * 2 + 1]);
        }
    }

    // ---- reduce l across lane quads and the 2 key-partition warps ----
    float* sl = (float*)(smc + SLB);
    #pragma unroll
    for (int mi = 0; mi < 2; mi++) {
        #pragma unroll
        for (int hh = 0; hh < 2; hh++) {
            float v = lsum[mi][hh];
            v += __shfl_xor_sync(0xFFFFFFFFu, v, 1);
            v += __shfl_xor_sync(0xFFFFFFFFu, v, 2);
            if (tig == 0)
                sl[wn * 128 + wm * 32 + mi * 16 + hh * 8 + gid] = v;
        }
    }
    __syncthreads();

    // ---- normalize and write out (fp32 g_ao) ----
    #pragma unroll
    for (int mi = 0; mi < 2; mi++) {
        #pragma unroll
        for (int ni = 0; ni < 4; ni++) {
            const int rowl = wm * 32 + mi * 16 + gid;
            const int col = wn * 32 + ni * 8 + 2 * tig;
            #pragma unroll
            for (int hh = 0; hh < 2; hh++) {
                const int r = rowl + hh * 8;
                const float linv = 1.f / (sl[r] + sl[128 + r]);
                float2 v;
                v.x = acc[mi][ni][hh * 2 + 0] * linv;
                v.y = acc[mi][ni][hh * 2 + 1] * linv;
                *(float2*)&g_ao[((size_t)(b * Nd + q0 + r)) * Cd + h * HDd + col] = v;
            }
        }
    }
}

// ---------------- k mean over heads ----------------------------------------
__global__ __launch_bounds__(256)
void kmean_kernel(float* __restrict__ out)
{
    const int idx = blockIdx.x * 256 + threadIdx.x;
    if (idx >= Bd * Nd * HDd) return;
    const int hd = idx & 63;
    const int n  = (idx >> 6) & 2047;
    const int b  = idx >> 17;
    float s = 0.f;
    #pragma unroll
    for (int h = 0; h < Hd; h++)
        s += g_k[(((size_t)(b * Hd + h)) * Nd + n) * HDd + hd];
    out[idx] = s * (1.0f / Hd);
}

// ---------------- launch ----------------------------------------------------
extern "C" void kernel_launch(void* const* d_in, const int* in_sizes, int n_in,
                              void* d_out, int out_size)
{
    const float* x    = (const float*)d_in[0];
    const float* size = (const float*)d_in[1];
    const float* q_w  = (const float*)d_in[2];
    const float* q_b  = (const float*)d_in[3];
    const float* k_w  = (const float*)d_in[4];
    const float* k_b  = (const float*)d_in[5];
    const float* v_w  = (const float*)d_in[6];
    const float* v_b  = (const float*)d_in[7];
    const float* o_w  = (const float*)d_in[8];
    const float* o_b  = (const float*)d_in[9];

    float* out   = (float*)d_out;
    float* kmean = out + (size_t)Bd * Nd * Cd;

    cudaFuncSetAttribute(attn_fp16, cudaFuncAttributeMaxDynamicSharedMemorySize,
                         ASM_TOTAL);

    dim3 gqkv(Cd / 128, (Bd * Nd) / 128, 3);
    gemm_qkv_tf32<<<gqkv, 256>>>(x, q_w, k_w, v_w, q_b, k_b, v_b);

    kmean_kernel<<<(Bd * Nd * HDd + 255) / 256, 256>>>(kmean);

    dim3 gat(Bd * Hd, Nd / 128);
    attn_fp16<<<gat, 256, ASM_TOTAL>>>(size);

    dim3 go(Cd / 128, (Bd * Nd) / 128, 1);
    gemm_o_tf32<<<go, 256>>>(o_w, o_b, out);
}

// round 6
// speedup vs baseline: 5.2898x; 1.0965x over previous
#include <cuda_runtime.h>
#include <cuda_fp16.h>
#include <math.h>
#include <cstdint>

#define Bd 8
#define Nd 2048
#define Cd 768
#define Hd 12
#define HDd 64
#define SCALEf 0.125f

// ---------------- scratch ----------------
__device__ __half g_qh[Bd * Hd * Nd * HDd];    // fp16, pre-scaled by 0.125
__device__ __half g_kh[Bd * Hd * Nd * HDd];
__device__ __half g_vh[Bd * Hd * Nd * HDd];
__device__ float g_ao[Bd * Nd * Cd];

// ---------------- helpers ----------------
__device__ __forceinline__ uint32_t smem_u32(const void* p) {
    uint32_t a;
    asm("{ .reg .u64 t; cvta.to.shared.u64 t, %1; cvt.u32.u64 %0, t; }"
        : "=r"(a) : "l"(p));
    return a;
}

__device__ __forceinline__ void mmah(float* c,
                                     unsigned a0, unsigned a1, unsigned a2, unsigned a3,
                                     unsigned b0, unsigned b1) {
    asm volatile(
        "mma.sync.aligned.m16n8k16.row.col.f32.f16.f16.f32 "
        "{%0,%1,%2,%3}, {%4,%5,%6,%7}, {%8,%9}, {%0,%1,%2,%3};"
        : "+f"(c[0]), "+f"(c[1]), "+f"(c[2]), "+f"(c[3])
        : "r"(a0), "r"(a1), "r"(a2), "r"(a3), "r"(b0), "r"(b1));
}

#define LDM_X4(r0, r1, r2, r3, addr) \
    asm volatile("ldmatrix.sync.aligned.m8n8.x4.shared.b16 {%0,%1,%2,%3}, [%4];" \
                 : "=r"(r0), "=r"(r1), "=r"(r2), "=r"(r3) : "r"(addr))

#define LDM_X4T(r0, r1, r2, r3, addr) \
    asm volatile("ldmatrix.sync.aligned.m8n8.x4.trans.shared.b16 {%0,%1,%2,%3}, [%4];" \
                 : "=r"(r0), "=r"(r1), "=r"(r2), "=r"(r3) : "r"(addr))

#define SWZ(x) ((x) ^ (((x) >> 3) & 0x70))

__device__ __forceinline__ uint32_t packh(float a, float b) {
    __half2 t = __floats2half2_rn(a, b);
    return *reinterpret_cast<uint32_t*>(&t);
}

// ================= fp16 GEMM: y[m,d] = sum_c A[m,c]*W[d,c] + bias[d] =======
// 256 threads (8 warps: wm in {0,1} x 64 rows, wn in {0..3} x 32 cols).
// K chunks of 64 halves (= 128B rows, SW128). 12 chunks for Cd=768.
// smem: A tile 16KB @0, B tile 16KB @16384.

template <class Epi>
__device__ __forceinline__ void gemm_h_body(const float* __restrict__ A,
                                            const float* __restrict__ W,
                                            int m0, int n0, const Epi& epi)
{
    __shared__ char smc[32768];
    const uint32_t sb = smem_u32(smc);

    const int tid = threadIdx.x, lane = tid & 31, warp = tid >> 5;
    const int wm = warp >> 2, wn = warp & 3;
    const int gid = lane >> 2, tig = lane & 3;

    // ldmatrix lane addressing (same as attention kernel)
    const int a_row = (lane & 15);
    const int a_bc  = (lane >> 4) << 4;
    const int b_row = (lane & 7) + ((lane >> 4) << 3);
    const int b_bc  = ((lane >> 3) & 1) << 4;

    float acc[4][4][4];
    #pragma unroll
    for (int i = 0; i < 4; i++)
        #pragma unroll
        for (int j = 0; j < 4; j++)
            #pragma unroll
            for (int r = 0; r < 4; r++) acc[i][j][r] = 0.f;

    // stage mapping: 4 passes x 256 threads cover 1024 16B-segments per tile
    for (int c = 0; c < Cd / 64; c++) {
        const int k0 = c * 64;
        __syncthreads();
        #pragma unroll
        for (int p = 0; p < 4; p++) {
            const int sidx = tid + p * 256;
            const int row = sidx >> 3, seg = sidx & 7;
            const float4 fa0 = *(const float4*)(A + (size_t)(m0 + row) * Cd + k0 + seg * 8);
            const float4 fa1 = *(const float4*)(A + (size_t)(m0 + row) * Cd + k0 + seg * 8 + 4);
            const float4 fb0 = *(const float4*)(W + (size_t)(n0 + row) * Cd + k0 + seg * 8);
            const float4 fb1 = *(const float4*)(W + (size_t)(n0 + row) * Cd + k0 + seg * 8 + 4);
            uint4 ua, ub;
            ua.x = packh(fa0.x, fa0.y); ua.y = packh(fa0.z, fa0.w);
            ua.z = packh(fa1.x, fa1.y); ua.w = packh(fa1.z, fa1.w);
            ub.x = packh(fb0.x, fb0.y); ub.y = packh(fb0.z, fb0.w);
            ub.z = packh(fb1.x, fb1.y); ub.w = packh(fb1.z, fb1.w);
            *(uint4*)(smc + SWZ(row * 128 + seg * 16)) = ua;
            *(uint4*)(smc + 16384 + SWZ(row * 128 + seg * 16)) = ub;
        }
        __syncthreads();

        #pragma unroll
        for (int ks = 0; ks < 4; ks++) {
            uint32_t a[4][4], bk[2][4];
            #pragma unroll
            for (int mi = 0; mi < 4; mi++) {
                const int row = wm * 64 + mi * 16 + a_row;
                LDM_X4(a[mi][0], a[mi][1], a[mi][2], a[mi][3],
                       sb + SWZ(row * 128 + ks * 32 + a_bc));
            }
            #pragma unroll
            for (int nh = 0; nh < 2; nh++) {
                const int row = wn * 32 + nh * 16 + b_row;
                LDM_X4(bk[nh][0], bk[nh][1], bk[nh][2], bk[nh][3],
                       sb + 16384 + SWZ(row * 128 + ks * 32 + b_bc));
            }
            #pragma unroll
            for (int mi = 0; mi < 4; mi++)
                #pragma unroll
                for (int ni = 0; ni < 4; ni++)
                    mmah(acc[mi][ni], a[mi][0], a[mi][1], a[mi][2], a[mi][3],
                         bk[ni >> 1][(ni & 1) * 2], bk[ni >> 1][(ni & 1) * 2 + 1]);
        }
    }

    // epilogue
    #pragma unroll
    for (int mi = 0; mi < 4; mi++)
        #pragma unroll
        for (int ni = 0; ni < 4; ni++)
            epi.emit(wm * 64 + mi * 16 + gid, wn * 32 + ni * 8 + 2 * tig, acc[mi][ni]);
}

struct EpiQKV {
    __half* outb; const float* bias; int m0, n0; float mult;
    __device__ __forceinline__ void emit(int rl, int cl, const float* a) const {
        const int col = n0 + cl;
        const float b0v = bias[col], b1v = bias[col + 1];
        const int h = col >> 6, hd = col & 63;
        #pragma unroll
        for (int hh = 0; hh < 2; hh++) {
            const int r = m0 + rl + hh * 8;
            const int bb = r >> 11, n = r & 2047;
            const size_t idx = (((size_t)(bb * Hd + h)) * Nd + n) * HDd + hd;
            *(uint32_t*)&outb[idx] = packh((a[hh * 2 + 0] + b0v) * mult,
                                           (a[hh * 2 + 1] + b1v) * mult);
        }
    }
};

struct EpiO {
    float* outp; const float* bias; int m0, n0;
    __device__ __forceinline__ void emit(int rl, int cl, const float* a) const {
        const int col = n0 + cl;
        const float b0v = bias[col], b1v = bias[col + 1];
        #pragma unroll
        for (int hh = 0; hh < 2; hh++) {
            const int r = m0 + rl + hh * 8;
            float2 v;
            v.x = a[hh * 2 + 0] + b0v;
            v.y = a[hh * 2 + 1] + b1v;
            *(float2*)&outp[(size_t)r * Cd + col] = v;
        }
    }
};

__global__ __launch_bounds__(256)
void gemm_qkv_h(const float* __restrict__ x,
                const float* __restrict__ wq, const float* __restrict__ wk,
                const float* __restrict__ wv,
                const float* __restrict__ bq, const float* __restrict__ bk,
                const float* __restrict__ bv)
{
    const int z = blockIdx.z;
    const float* W    = (z == 0) ? wq : (z == 1) ? wk : wv;
    const float* bias = (z == 0) ? bq : (z == 1) ? bk : bv;
    __half* outb      = (z == 0) ? g_qh : (z == 1) ? g_kh : g_vh;
    EpiQKV e{outb, bias, (int)blockIdx.y * 128, (int)blockIdx.x * 128,
             (z == 0) ? SCALEf : 1.0f};
    gemm_h_body(x, W, e.m0, e.n0, e);
}

__global__ __launch_bounds__(256)
void gemm_o_h(const float* __restrict__ W, const float* __restrict__ bias,
              float* __restrict__ out)
{
    EpiO e{out, bias, (int)blockIdx.y * 128, (int)blockIdx.x * 128};
    gemm_h_body(g_ao, W, e.m0, e.n0, e);
}

// ================= attention: fp16 mma + ldmatrix (R5-proven) ==============
#define QS 0
#define KS 16384
#define VS 24576
#define PS 32768
#define SZB 49152
#define SLB 49408
#define ASM_TOTAL 50432

__global__ __launch_bounds__(256)
void attn_fp16(const float* __restrict__ size)
{
    extern __shared__ char smc[];
    const uint32_t sb = smem_u32(smc);

    const int bh = blockIdx.x;
    const int b = bh / Hd, h = bh % Hd;
    const int q0 = blockIdx.y * 128;
    const int tid = threadIdx.x, lane = tid & 31, warp = tid >> 5;
    const int wm = warp >> 1;
    const int wn = warp & 1;
    const int gid = lane >> 2, tig = lane & 3;

    const char* qb = (const char*)(g_qh + ((size_t)bh * Nd + q0) * HDd);
    #pragma unroll
    for (int i = 0; i < 4; i++) {
        const int f = tid + i * 256;
        const int row = f >> 3, seg = (f & 7) * 16;
        *(uint4*)(smc + QS + SWZ(row * 128 + seg)) =
            *(const uint4*)(qb + (size_t)row * 128 + seg);
    }

    const char* kbb = (const char*)(g_kh + (size_t)bh * Nd * HDd);
    const char* vbb = (const char*)(g_vh + (size_t)bh * Nd * HDd);
    const float* sbase = size + (size_t)b * Nd;

    float acc[2][4][4];
    #pragma unroll
    for (int i = 0; i < 2; i++)
        #pragma unroll
        for (int j = 0; j < 4; j++)
            #pragma unroll
            for (int r = 0; r < 4; r++) acc[i][j][r] = 0.f;
    float lsum[2][2] = {{0.f, 0.f}, {0.f, 0.f}};

    const int a_row = (lane & 15);
    const int a_bc  = (lane >> 4) << 4;
    const int b_row = (lane & 7) + ((lane >> 4) << 3);
    const int b_bc  = ((lane >> 3) & 1) << 4;
    const int v_row = (lane & 7) + (((lane >> 3) & 1) << 3);
    const int v_bc  = (lane >> 4) << 4;

    for (int kc = 0; kc < Nd; kc += 64) {
        __syncthreads();
        #pragma unroll
        for (int i = 0; i < 2; i++) {
            const int f = tid + i * 256;
            const int row = f >> 3, seg = (f & 7) * 16;
            *(uint4*)(smc + KS + SWZ(row * 128 + seg)) =
                *(const uint4*)(kbb + ((size_t)(kc + row)) * 128 + seg);
            *(uint4*)(smc + VS + SWZ(row * 128 + seg)) =
                *(const uint4*)(vbb + ((size_t)(kc + row)) * 128 + seg);
        }
        if (tid < 64) *(float*)(smc + SZB + tid * 4) = sbase[kc + tid];
        __syncthreads();

        float sc[2][4][4];
        #pragma unroll
        for (int i = 0; i < 2; i++)
            #pragma unroll
            for (int j = 0; j < 4; j++)
                #pragma unroll
                for (int r = 0; r < 4; r++) sc[i][j][r] = 0.f;

        #pragma unroll
        for (int ks = 0; ks < 4; ks++) {
            uint32_t a[2][4], bk[2][4];
            #pragma unroll
            for (int mi = 0; mi < 2; mi++) {
                const int row = wm * 32 + mi * 16 + a_row;
                LDM_X4(a[mi][0], a[mi][1], a[mi][2], a[mi][3],
                       sb + QS + SWZ(row * 128 + ks * 32 + a_bc));
            }
            #pragma unroll
            for (int nh = 0; nh < 2; nh++) {
                const int row = wn * 32 + nh * 16 + b_row;
                LDM_X4(bk[nh][0], bk[nh][1], bk[nh][2], bk[nh][3],
                       sb + KS + SWZ(row * 128 + ks * 32 + b_bc));
            }
            #pragma unroll
            for (int mi = 0; mi < 2; mi++)
                #pragma unroll
                for (int ni = 0; ni < 4; ni++)
                    mmah(sc[mi][ni], a[mi][0], a[mi][1], a[mi][2], a[mi][3],
                         bk[ni >> 1][(ni & 1) * 2], bk[ni >> 1][(ni & 1) * 2 + 1]);
        }

        #pragma unroll
        for (int mi = 0; mi < 2; mi++) {
            #pragma unroll
            for (int ni = 0; ni < 4; ni++) {
                const int row = wm * 32 + mi * 16 + gid;
                const int col = wn * 32 + ni * 8 + 2 * tig;
                const float sz0 = *(const float*)(smc + SZB + col * 4);
                const float sz1 = *(const float*)(smc + SZB + col * 4 + 4);
                const float p0 = sz0 * __expf(sc[mi][ni][0]);
                const float p1 = sz1 * __expf(sc[mi][ni][1]);
                const float p2 = sz0 * __expf(sc[mi][ni][2]);
                const float p3 = sz1 * __expf(sc[mi][ni][3]);
                lsum[mi][0] += p0 + p1;
                lsum[mi][1] += p2 + p3;
                *(uint32_t*)(smc + PS + SWZ(row * 128 + col * 2)) = packh(p0, p1);
                *(uint32_t*)(smc + PS + SWZ((row + 8) * 128 + col * 2)) = packh(p2, p3);
            }
        }
        __syncthreads();

        #pragma unroll
        for (int ks = 0; ks < 4; ks++) {
            uint32_t a[2][4], bv[2][4];
            #pragma unroll
            for (int mi = 0; mi < 2; mi++) {
                const int row = wm * 32 + mi * 16 + a_row;
                LDM_X4(a[mi][0], a[mi][1], a[mi][2], a[mi][3],
                       sb + PS + SWZ(row * 128 + ks * 32 + a_bc));
            }
            #pragma unroll
            for (int dh = 0; dh < 2; dh++) {
                const int row = ks * 16 + v_row;
                const int bcol = (wn * 32 + dh * 16) * 2 + v_bc;
                LDM_X4T(bv[dh][0], bv[dh][1], bv[dh][2], bv[dh][3],
                        sb + VS + SWZ(row * 128 + bcol));
            }
            #pragma unroll
            for (int mi = 0; mi < 2; mi++)
                #pragma unroll
                for (int ni = 0; ni < 4; ni++)
                    mmah(acc[mi][ni], a[mi][0], a[mi][1], a[mi][2], a[mi][3],
                         bv[ni >> 1][(ni & 1) * 2], bv[ni >> 1][(ni & 1) * 2 + 1]);
        }
    }

    float* sl = (float*)(smc + SLB);
    #pragma unroll
    for (int mi = 0; mi < 2; mi++) {
        #pragma unroll
        for (int hh = 0; hh < 2; hh++) {
            float v = lsum[mi][hh];
            v += __shfl_xor_sync(0xFFFFFFFFu, v, 1);
            v += __shfl_xor_sync(0xFFFFFFFFu, v, 2);
            if (tig == 0)
                sl[wn * 128 + wm * 32 + mi * 16 + hh * 8 + gid] = v;
        }
    }
    __syncthreads();

    #pragma unroll
    for (int mi = 0; mi < 2; mi++) {
        #pragma unroll
        for (int ni = 0; ni < 4; ni++) {
            const int rowl = wm * 32 + mi * 16 + gid;
            const int col = wn * 32 + ni * 8 + 2 * tig;
            #pragma unroll
            for (int hh = 0; hh < 2; hh++) {
                const int r = rowl + hh * 8;
                const float linv = 1.f / (sl[r] + sl[128 + r]);
                float2 v;
                v.x = acc[mi][ni][hh * 2 + 0] * linv;
                v.y = acc[mi][ni][hh * 2 + 1] * linv;
                *(float2*)&g_ao[((size_t)(b * Nd + q0 + r)) * Cd + h * HDd + col] = v;
            }
        }
    }
}

// ---------------- k mean over heads (from fp16 k) ---------------------------
__global__ __launch_bounds__(256)
void kmean_kernel(float* __restrict__ out)
{
    const int idx = blockIdx.x * 256 + threadIdx.x;
    if (idx >= Bd * Nd * HDd) return;
    const int hd = idx & 63;
    const int n  = (idx >> 6) & 2047;
    const int b  = idx >> 17;
    float s = 0.f;
    #pragma unroll
    for (int h = 0; h < Hd; h++)
        s += __half2float(g_kh[(((size_t)(b * Hd + h)) * Nd + n) * HDd + hd]);
    out[idx] = s * (1.0f / Hd);
}

// ---------------- launch ----------------------------------------------------
extern "C" void kernel_launch(void* const* d_in, const int* in_sizes, int n_in,
                              void* d_out, int out_size)
{
    const float* x    = (const float*)d_in[0];
    const float* size = (const float*)d_in[1];
    const float* q_w  = (const float*)d_in[2];
    const float* q_b  = (const float*)d_in[3];
    const float* k_w  = (const float*)d_in[4];
    const float* k_b  = (const float*)d_in[5];
    const float* v_w  = (const float*)d_in[6];
    const float* v_b  = (const float*)d_in[7];
    const float* o_w  = (const float*)d_in[8];
    const float* o_b  = (const float*)d_in[9];

    float* out   = (float*)d_out;
    float* kmean = out + (size_t)Bd * Nd * Cd;

    cudaFuncSetAttribute(attn_fp16, cudaFuncAttributeMaxDynamicSharedMemorySize,
                         ASM_TOTAL);

    dim3 gqkv(Cd / 128, (Bd * Nd) / 128, 3);
    gemm_qkv_h<<<gqkv, 256>>>(x, q_w, k_w, v_w, q_b, k_b, v_b);

    kmean_kernel<<<(Bd * Nd * HDd + 255) / 256, 256>>>(kmean);

    dim3 gat(Bd * Hd, Nd / 128);
    attn_fp16<<<gat, 256, ASM_TOTAL>>>(size);

    dim3 go(Cd / 128, (Bd * Nd) / 128, 1);
    gemm_o_h<<<go, 256>>>(o_w, o_b, out);
}

// round 7
// speedup vs baseline: 8.3290x; 1.5745x over previous
#include <cuda_runtime.h>
#include <cuda_fp16.h>
#include <math.h>
#include <cstdint>

#define Bd 8
#define Nd 2048
#define Cd 768
#define Hd 12
#define HDd 64
#define SCALEf 0.125f

// ---------------- scratch ----------------
__device__ __half g_xh[Bd * Nd * Cd];          // fp16 x
__device__ __half g_wh[4][Cd * Cd];            // fp16 weights q,k,v,o
__device__ __half g_qh[Bd * Hd * Nd * HDd];    // fp16, pre-scaled by 0.125
__device__ __half g_kh[Bd * Hd * Nd * HDd];
__device__ __half g_vh[Bd * Hd * Nd * HDd];
__device__ __half g_aoh[Bd * Nd * Cd];         // fp16 attention output

// ---------------- helpers ----------------
__device__ __forceinline__ uint32_t smem_u32(const void* p) {
    uint32_t a;
    asm("{ .reg .u64 t; cvta.to.shared.u64 t, %1; cvt.u32.u64 %0, t; }"
        : "=r"(a) : "l"(p));
    return a;
}

__device__ __forceinline__ void mmah(float* c,
                                     unsigned a0, unsigned a1, unsigned a2, unsigned a3,
                                     unsigned b0, unsigned b1) {
    asm volatile(
        "mma.sync.aligned.m16n8k16.row.col.f32.f16.f16.f32 "
        "{%0,%1,%2,%3}, {%4,%5,%6,%7}, {%8,%9}, {%0,%1,%2,%3};"
        : "+f"(c[0]), "+f"(c[1]), "+f"(c[2]), "+f"(c[3])
        : "r"(a0), "r"(a1), "r"(a2), "r"(a3), "r"(b0), "r"(b1));
}

#define LDM_X4(r0, r1, r2, r3, addr) \
    asm volatile("ldmatrix.sync.aligned.m8n8.x4.shared.b16 {%0,%1,%2,%3}, [%4];" \
                 : "=r"(r0), "=r"(r1), "=r"(r2), "=r"(r3) : "r"(addr))

#define LDM_X4T(r0, r1, r2, r3, addr) \
    asm volatile("ldmatrix.sync.aligned.m8n8.x4.trans.shared.b16 {%0,%1,%2,%3}, [%4];" \
                 : "=r"(r0), "=r"(r1), "=r"(r2), "=r"(r3) : "r"(addr))

#define SWZ(x) ((x) ^ (((x) >> 3) & 0x70))

#define CP16(dst, src) \
    asm volatile("cp.async.cg.shared.global [%0], [%1], 16;" \
                 :: "r"(dst), "l"(src) : "memory")
#define CP_COMMIT() asm volatile("cp.async.commit_group;" ::: "memory")
#define CP_WAIT1() asm volatile("cp.async.wait_group 1;" ::: "memory")

__device__ __forceinline__ uint32_t packh(float a, float b) {
    __half2 t = __floats2half2_rn(a, b);
    return *reinterpret_cast<uint32_t*>(&t);
}

// ---------------- f32 -> f16 convert (8 elems/thread) ----------------------
__global__ __launch_bounds__(256)
void cvt_h_kernel(const float* __restrict__ src, __half* __restrict__ dst, int n)
{
    const int i8 = (blockIdx.x * 256 + threadIdx.x) * 8;
    if (i8 >= n) return;
    const float4 a = *(const float4*)(src + i8);
    const float4 b = *(const float4*)(src + i8 + 4);
    uint4 u;
    u.x = packh(a.x, a.y); u.y = packh(a.z, a.w);
    u.z = packh(b.x, b.y); u.w = packh(b.z, b.w);
    *(uint4*)(dst + i8) = u;
}

// ================= fp16 GEMM, cp.async double-buffered =====================
// 256 threads (8 warps: wm {0,1} x 64 rows, wn {0..3} x 32 cols).
// K chunks of 64 halves (128B rows, SW128). NC = 12 chunks.
// dyn smem: A0@0, A1@16384, B0@32768, B1@49152 (16KB each) = 64KB.
#define GNC (Cd / 64)
#define GSMB 65536

__device__ __forceinline__ void gemm_stage(const __half* __restrict__ Ab,
                                           const __half* __restrict__ Wb,
                                           uint32_t sb, int buf, int tid)
{
    const uint32_t ab = sb + (buf ? 16384u : 0u);
    const uint32_t bb = sb + 32768u + (buf ? 16384u : 0u);
    #pragma unroll
    for (int p = 0; p < 4; p++) {
        const int s = tid + p * 256;
        const int row = s >> 3, seg = s & 7;
        CP16(ab + SWZ(row * 128 + seg * 16), Ab + (size_t)row * Cd + seg * 8);
    }
    #pragma unroll
    for (int p = 0; p < 4; p++) {
        const int s = tid + p * 256;
        const int row = s >> 3, seg = s & 7;
        CP16(bb + SWZ(row * 128 + seg * 16), Wb + (size_t)row * Cd + seg * 8);
    }
}

template <class Epi>
__device__ __forceinline__ void gemm_h2_body(const __half* __restrict__ A,
                                             const __half* __restrict__ W,
                                             int m0, int n0, const Epi& epi)
{
    extern __shared__ char smc[];
    const uint32_t sb = smem_u32(smc);

    const int tid = threadIdx.x, lane = tid & 31, warp = tid >> 5;
    const int wm = warp >> 2, wn = warp & 3;
    const int gid = lane >> 2, tig = lane & 3;

    const int a_row = (lane & 15);
    const int a_bc  = (lane >> 4) << 4;
    const int b_row = (lane & 7) + ((lane >> 4) << 3);
    const int b_bc  = ((lane >> 3) & 1) << 4;

    float acc[4][4][4];
    #pragma unroll
    for (int i = 0; i < 4; i++)
        #pragma unroll
        for (int j = 0; j < 4; j++)
            #pragma unroll
            for (int r = 0; r < 4; r++) acc[i][j][r] = 0.f;

    const __half* Abase = A + (size_t)m0 * Cd;
    const __half* Wbase = W + (size_t)n0 * Cd;

    // prologue: chunks 0,1
    gemm_stage(Abase, Wbase, sb, 0, tid);
    CP_COMMIT();
    gemm_stage(Abase + 64, Wbase + 64, sb, 1, tid);
    CP_COMMIT();

    for (int c = 0; c < GNC; c++) {
        const int buf = c & 1;
        CP_WAIT1();
        __syncthreads();

        const uint32_t ab = sb + (buf ? 16384u : 0u);
        const uint32_t bb = sb + 32768u + (buf ? 16384u : 0u);
        #pragma unroll
        for (int ks = 0; ks < 4; ks++) {
            uint32_t a[4][4], bk[2][4];
            #pragma unroll
            for (int mi = 0; mi < 4; mi++) {
                const int row = wm * 64 + mi * 16 + a_row;
                LDM_X4(a[mi][0], a[mi][1], a[mi][2], a[mi][3],
                       ab + SWZ(row * 128 + ks * 32 + a_bc));
            }
            #pragma unroll
            for (int nh = 0; nh < 2; nh++) {
                const int row = wn * 32 + nh * 16 + b_row;
                LDM_X4(bk[nh][0], bk[nh][1], bk[nh][2], bk[nh][3],
                       bb + SWZ(row * 128 + ks * 32 + b_bc));
            }
            #pragma unroll
            for (int mi = 0; mi < 4; mi++)
                #pragma unroll
                for (int ni = 0; ni < 4; ni++)
                    mmah(acc[mi][ni], a[mi][0], a[mi][1], a[mi][2], a[mi][3],
                         bk[ni >> 1][(ni & 1) * 2], bk[ni >> 1][(ni & 1) * 2 + 1]);
        }
        __syncthreads();

        if (c + 2 < GNC)
            gemm_stage(Abase + (c + 2) * 64, Wbase + (c + 2) * 64, sb, buf, tid);
        CP_COMMIT();
    }

    #pragma unroll
    for (int mi = 0; mi < 4; mi++)
        #pragma unroll
        for (int ni = 0; ni < 4; ni++)
            epi.emit(wm * 64 + mi * 16 + gid, wn * 32 + ni * 8 + 2 * tig, acc[mi][ni]);
}

struct EpiQKV {
    __half* outb; const float* bias; int m0, n0; float mult;
    __device__ __forceinline__ void emit(int rl, int cl, const float* a) const {
        const int col = n0 + cl;
        const float b0v = bias[col], b1v = bias[col + 1];
        const int h = col >> 6, hd = col & 63;
        #pragma unroll
        for (int hh = 0; hh < 2; hh++) {
            const int r = m0 + rl + hh * 8;
            const int bb = r >> 11, n = r & 2047;
            const size_t idx = (((size_t)(bb * Hd + h)) * Nd + n) * HDd + hd;
            *(uint32_t*)&outb[idx] = packh((a[hh * 2 + 0] + b0v) * mult,
                                           (a[hh * 2 + 1] + b1v) * mult);
        }
    }
};

struct EpiO {
    float* outp; const float* bias; int m0, n0;
    __device__ __forceinline__ void emit(int rl, int cl, const float* a) const {
        const int col = n0 + cl;
        const float b0v = bias[col], b1v = bias[col + 1];
        #pragma unroll
        for (int hh = 0; hh < 2; hh++) {
            const int r = m0 + rl + hh * 8;
            float2 v;
            v.x = a[hh * 2 + 0] + b0v;
            v.y = a[hh * 2 + 1] + b1v;
            *(float2*)&outp[(size_t)r * Cd + col] = v;
        }
    }
};

__global__ __launch_bounds__(256)
void gemm_qkv_h2(const float* __restrict__ bq, const float* __restrict__ bk,
                 const float* __restrict__ bv)
{
    const int z = blockIdx.z;
    const float* bias = (z == 0) ? bq : (z == 1) ? bk : bv;
    __half* outb      = (z == 0) ? g_qh : (z == 1) ? g_kh : g_vh;
    EpiQKV e{outb, bias, (int)blockIdx.y * 128, (int)blockIdx.x * 128,
             (z == 0) ? SCALEf : 1.0f};
    gemm_h2_body(g_xh, g_wh[z], e.m0, e.n0, e);
}

__global__ __launch_bounds__(256)
void gemm_o_h2(const float* __restrict__ bias, float* __restrict__ out)
{
    EpiO e{out, bias, (int)blockIdx.y * 128, (int)blockIdx.x * 128};
    gemm_h2_body(g_aoh, g_wh[3], e.m0, e.n0, e);
}

// ================= attention: fp16 mma + cp.async ring-3 ===================
// dyn smem bytes:
//   Q 16KB @0; K slots 8KB @16384+s*8192; V slots 8KB @40960+s*8192;
//   P 16KB @65536; SZ 256B @81920+s*256; SL @82688. total 83712.
#define AQS 0
#define AKS 16384
#define AVS 40960
#define APS 65536
#define ASZ 81920
#define ASL 82688
#define ASMB 83712
#define ANC (Nd / 64)

__global__ __launch_bounds__(256)
void attn_fp16(const float* __restrict__ size)
{
    extern __shared__ char smc[];
    const uint32_t sb = smem_u32(smc);

    const int bh = blockIdx.x;
    const int b = bh / Hd, h = bh % Hd;
    const int q0 = blockIdx.y * 128;
    const int tid = threadIdx.x, lane = tid & 31, warp = tid >> 5;
    const int wm = warp >> 1;
    const int wn = warp & 1;
    const int gid = lane >> 2, tig = lane & 3;

    const __half* qb  = g_qh + ((size_t)bh * Nd + q0) * HDd;
    const __half* kbb = g_kh + (size_t)bh * Nd * HDd;
    const __half* vbb = g_vh + (size_t)bh * Nd * HDd;
    const float* sbase = size + (size_t)b * Nd;

    // stage a K/V/size chunk into ring slot
    auto stage_kv = [&](int c, int slot) {
        const __half* Kb = kbb + (size_t)c * 64 * HDd;
        const __half* Vb = vbb + (size_t)c * 64 * HDd;
        const uint32_t kdst = sb + AKS + slot * 8192;
        const uint32_t vdst = sb + AVS + slot * 8192;
        #pragma unroll
        for (int p = 0; p < 2; p++) {
            const int s = tid + p * 256;
            const int row = s >> 3, seg = s & 7;
            CP16(kdst + SWZ(row * 128 + seg * 16), Kb + (size_t)row * HDd + seg * 8);
        }
        #pragma unroll
        for (int p = 0; p < 2; p++) {
            const int s = tid + p * 256;
            const int row = s >> 3, seg = s & 7;
            CP16(vdst + SWZ(row * 128 + seg * 16), Vb + (size_t)row * HDd + seg * 8);
        }
        if (tid < 16)
            CP16(sb + ASZ + slot * 256 + tid * 16, sbase + c * 64 + tid * 4);
    };

    // prologue: Q + chunk0 in group0; chunk1 in group1
    #pragma unroll
    for (int p = 0; p < 4; p++) {
        const int s = tid + p * 256;
        const int row = s >> 3, seg = s & 7;
        CP16(sb + AQS + SWZ(row * 128 + seg * 16), qb + (size_t)row * HDd + seg * 8);
    }
    stage_kv(0, 0);
    CP_COMMIT();
    stage_kv(1, 1);
    CP_COMMIT();

    float acc[2][4][4];
    #pragma unroll
    for (int i = 0; i < 2; i++)
        #pragma unroll
        for (int j = 0; j < 4; j++)
            #pragma unroll
            for (int r = 0; r < 4; r++) acc[i][j][r] = 0.f;
    float lsum[2][2] = {{0.f, 0.f}, {0.f, 0.f}};

    const int a_row = (lane & 15);
    const int a_bc  = (lane >> 4) << 4;
    const int b_row = (lane & 7) + ((lane >> 4) << 3);
    const int b_bc  = ((lane >> 3) & 1) << 4;
    const int v_row = (lane & 7) + (((lane >> 3) & 1) << 3);
    const int v_bc  = (lane >> 4) << 4;

    for (int c = 0; c < ANC; c++) {
        const int slot = c % 3;
        CP_WAIT1();
        __syncthreads();

        // issue c+2 into slot (c+2)%3 (last read in iter c-1; safe after sync)
        if (c + 2 < ANC) stage_kv(c + 2, (c + 2) % 3);
        CP_COMMIT();

        const uint32_t kbase = sb + AKS + slot * 8192;
        const uint32_t vbase = sb + AVS + slot * 8192;
        const uint32_t szb   = sb + ASZ + slot * 256;

        // ---- S = Q @ K^T ----
        float sc[2][4][4];
        #pragma unroll
        for (int i = 0; i < 2; i++)
            #pragma unroll
            for (int j = 0; j < 4; j++)
                #pragma unroll
                for (int r = 0; r < 4; r++) sc[i][j][r] = 0.f;

        #pragma unroll
        for (int ks = 0; ks < 4; ks++) {
            uint32_t a[2][4], bk[2][4];
            #pragma unroll
            for (int mi = 0; mi < 2; mi++) {
                const int row = wm * 32 + mi * 16 + a_row;
                LDM_X4(a[mi][0], a[mi][1], a[mi][2], a[mi][3],
                       sb + AQS + SWZ(row * 128 + ks * 32 + a_bc));
            }
            #pragma unroll
            for (int nh = 0; nh < 2; nh++) {
                const int row = wn * 32 + nh * 16 + b_row;
                LDM_X4(bk[nh][0], bk[nh][1], bk[nh][2], bk[nh][3],
                       kbase + SWZ(row * 128 + ks * 32 + b_bc));
            }
            #pragma unroll
            for (int mi = 0; mi < 2; mi++)
                #pragma unroll
                for (int ni = 0; ni < 4; ni++)
                    mmah(sc[mi][ni], a[mi][0], a[mi][1], a[mi][2], a[mi][3],
                         bk[ni >> 1][(ni & 1) * 2], bk[ni >> 1][(ni & 1) * 2 + 1]);
        }

        // ---- p = size_k * exp(s); store fp16 P; accumulate l ----
        #pragma unroll
        for (int mi = 0; mi < 2; mi++) {
            #pragma unroll
            for (int ni = 0; ni < 4; ni++) {
                const int row = wm * 32 + mi * 16 + gid;
                const int col = wn * 32 + ni * 8 + 2 * tig;
                float szv0, szv1;
                asm volatile("ld.shared.v2.f32 {%0,%1}, [%2];"
                             : "=f"(szv0), "=f"(szv1) : "r"(szb + col * 4));
                const float p0 = szv0 * __expf(sc[mi][ni][0]);
                const float p1 = szv1 * __expf(sc[mi][ni][1]);
                const float p2 = szv0 * __expf(sc[mi][ni][2]);
                const float p3 = szv1 * __expf(sc[mi][ni][3]);
                lsum[mi][0] += p0 + p1;
                lsum[mi][1] += p2 + p3;
                *(uint32_t*)(smc + APS + SWZ(row * 128 + col * 2)) = packh(p0, p1);
                *(uint32_t*)(smc + APS + SWZ((row + 8) * 128 + col * 2)) = packh(p2, p3);
            }
        }
        __syncthreads();

        // ---- O += P @ V ----
        #pragma unroll
        for (int ks = 0; ks < 4; ks++) {
            uint32_t a[2][4], bv[2][4];
            #pragma unroll
            for (int mi = 0; mi < 2; mi++) {
                const int row = wm * 32 + mi * 16 + a_row;
                LDM_X4(a[mi][0], a[mi][1], a[mi][2], a[mi][3],
                       sb + APS + SWZ(row * 128 + ks * 32 + a_bc));
            }
            #pragma unroll
            for (int dh = 0; dh < 2; dh++) {
                const int row = ks * 16 + v_row;
                const int bcol = (wn * 32 + dh * 16) * 2 + v_bc;
                LDM_X4T(bv[dh][0], bv[dh][1], bv[dh][2], bv[dh][3],
                        vbase + SWZ(row * 128 + bcol));
            }
            #pragma unroll
            for (int mi = 0; mi < 2; mi++)
                #pragma unroll
                for (int ni = 0; ni < 4; ni++)
                    mmah(acc[mi][ni], a[mi][0], a[mi][1], a[mi][2], a[mi][3],
                         bv[ni >> 1][(ni & 1) * 2], bv[ni >> 1][(ni & 1) * 2 + 1]);
        }
    }

    // ---- reduce l; normalize; write fp16 g_aoh ----
    float* sl = (float*)(smc + ASL);
    #pragma unroll
    for (int mi = 0; mi < 2; mi++) {
        #pragma unroll
        for (int hh = 0; hh < 2; hh++) {
            float v = lsum[mi][hh];
            v += __shfl_xor_sync(0xFFFFFFFFu, v, 1);
            v += __shfl_xor_sync(0xFFFFFFFFu, v, 2);
            if (tig == 0)
                sl[wn * 128 + wm * 32 + mi * 16 + hh * 8 + gid] = v;
        }
    }
    __syncthreads();

    #pragma unroll
    for (int mi = 0; mi < 2; mi++) {
        #pragma unroll
        for (int ni = 0; ni < 4; ni++) {
            const int rowl = wm * 32 + mi * 16 + gid;
            const int col = wn * 32 + ni * 8 + 2 * tig;
            #pragma unroll
            for (int hh = 0; hh < 2; hh++) {
                const int r = rowl + hh * 8;
                const float linv = 1.f / (sl[r] + sl[128 + r]);
                const size_t ofs = ((size_t)(b * Nd + q0 + r)) * Cd + h * HDd + col;
                *(uint32_t*)&g_aoh[ofs] = packh(acc[mi][ni][hh * 2 + 0] * linv,
                                                acc[mi][ni][hh * 2 + 1] * linv);
            }
        }
    }
}

// ---------------- k mean over heads (from fp16 k) ---------------------------
__global__ __launch_bounds__(256)
void kmean_kernel(float* __restrict__ out)
{
    const int idx = blockIdx.x * 256 + threadIdx.x;
    if (idx >= Bd * Nd * HDd) return;
    const int hd = idx & 63;
    const int n  = (idx >> 6) & 2047;
    const int b  = idx >> 17;
    float s = 0.f;
    #pragma unroll
    for (int h = 0; h < Hd; h++)
        s += __half2float(g_kh[(((size_t)(b * Hd + h)) * Nd + n) * HDd + hd]);
    out[idx] = s * (1.0f / Hd);
}

// ---------------- launch ----------------------------------------------------
extern "C" void kernel_launch(void* const* d_in, const int* in_sizes, int n_in,
                              void* d_out, int out_size)
{
    const float* x    = (const float*)d_in[0];
    const float* size = (const float*)d_in[1];
    const float* q_w  = (const float*)d_in[2];
    const float* q_b  = (const float*)d_in[3];
    const float* k_w  = (const float*)d_in[4];
    const float* k_b  = (const float*)d_in[5];
    const float* v_w  = (const float*)d_in[6];
    const float* v_b  = (const float*)d_in[7];
    const float* o_w  = (const float*)d_in[8];
    const float* o_b  = (const float*)d_in[9];

    float* out   = (float*)d_out;
    float* kmean = out + (size_t)Bd * Nd * Cd;

    cudaFuncSetAttribute(attn_fp16, cudaFuncAttributeMaxDynamicSharedMemorySize, ASMB);
    cudaFuncSetAttribute(gemm_qkv_h2, cudaFuncAttributeMaxDynamicSharedMemorySize, GSMB);
    cudaFuncSetAttribute(gemm_o_h2, cudaFuncAttributeMaxDynamicSharedMemorySize, GSMB);

    // resolve device-global addresses for convert targets
    __half* xh_p;  cudaGetSymbolAddress((void**)&xh_p, g_xh);
    __half* wh_p;  cudaGetSymbolAddress((void**)&wh_p, g_wh);

    const int nx = Bd * Nd * Cd;
    const int nw = Cd * Cd;
    cvt_h_kernel<<<(nx / 8 + 255) / 256, 256>>>(x, xh_p, nx);
    cvt_h_kernel<<<(nw / 8 + 255) / 256, 256>>>(q_w, wh_p + 0 * (size_t)nw, nw);
    cvt_h_kernel<<<(nw / 8 + 255) / 256, 256>>>(k_w, wh_p + 1 * (size_t)nw, nw);
    cvt_h_kernel<<<(nw / 8 + 255) / 256, 256>>>(v_w, wh_p + 2 * (size_t)nw, nw);
    cvt_h_kernel<<<(nw / 8 + 255) / 256, 256>>>(o_w, wh_p + 3 * (size_t)nw, nw);

    dim3 gqkv(Cd / 128, (Bd * Nd) / 128, 3);
    gemm_qkv_h2<<<gqkv, 256, GSMB>>>(q_b, k_b, v_b);

    kmean_kernel<<<(Bd * Nd * HDd + 255) / 256, 256>>>(kmean);

    dim3 gat(Bd * Hd, Nd / 128);
    attn_fp16<<<gat, 256, ASMB>>>(size);

    dim3 go(Cd / 128, (Bd * Nd) / 128, 1);
    gemm_o_h2<<<go, 256, GSMB>>>(o_b, out);
}

// round 8
// speedup vs baseline: 9.1279x; 1.0959x over previous
#include <cuda_runtime.h>
#include <cuda_fp16.h>
#include <math.h>
#include <cstdint>

#define Bd 8
#define Nd 2048
#define Cd 768
#define Hd 12
#define HDd 64
#define SCALEf 0.125f

// ---------------- scratch ----------------
__device__ __half g_xh[Bd * Nd * Cd];          // fp16 x
__device__ __half g_wh[4][Cd * Cd];            // fp16 weights q,k,v,o
__device__ __half g_qh[Bd * Hd * Nd * HDd];    // fp16, pre-scaled by 0.125
__device__ __half g_kh[Bd * Hd * Nd * HDd];
__device__ __half g_vh[Bd * Hd * Nd * HDd];
__device__ __half g_aoh[Bd * Nd * Cd];         // fp16 attention output

// ---------------- helpers ----------------
__device__ __forceinline__ uint32_t smem_u32(const void* p) {
    uint32_t a;
    asm("{ .reg .u64 t; cvta.to.shared.u64 t, %1; cvt.u32.u64 %0, t; }"
        : "=r"(a) : "l"(p));
    return a;
}

__device__ __forceinline__ void mmah(float* c,
                                     unsigned a0, unsigned a1, unsigned a2, unsigned a3,
                                     unsigned b0, unsigned b1) {
    asm volatile(
        "mma.sync.aligned.m16n8k16.row.col.f32.f16.f16.f32 "
        "{%0,%1,%2,%3}, {%4,%5,%6,%7}, {%8,%9}, {%0,%1,%2,%3};"
        : "+f"(c[0]), "+f"(c[1]), "+f"(c[2]), "+f"(c[3])
        : "r"(a0), "r"(a1), "r"(a2), "r"(a3), "r"(b0), "r"(b1));
}

#define LDM_X4(r0, r1, r2, r3, addr) \
    asm volatile("ldmatrix.sync.aligned.m8n8.x4.shared.b16 {%0,%1,%2,%3}, [%4];" \
                 : "=r"(r0), "=r"(r1), "=r"(r2), "=r"(r3) : "r"(addr))

#define LDM_X4T(r0, r1, r2, r3, addr) \
    asm volatile("ldmatrix.sync.aligned.m8n8.x4.trans.shared.b16 {%0,%1,%2,%3}, [%4];" \
                 : "=r"(r0), "=r"(r1), "=r"(r2), "=r"(r3) : "r"(addr))

#define SWZ(x) ((x) ^ (((x) >> 3) & 0x70))

#define CP16(dst, src) \
    asm volatile("cp.async.cg.shared.global [%0], [%1], 16;" \
                 :: "r"(dst), "l"(src) : "memory")
#define CP_COMMIT() asm volatile("cp.async.commit_group;" ::: "memory")
#define CP_WAIT1() asm volatile("cp.async.wait_group 1;" ::: "memory")

__device__ __forceinline__ uint32_t packh(float a, float b) {
    __half2 t = __floats2half2_rn(a, b);
    return *reinterpret_cast<uint32_t*>(&t);
}

// ---------------- f32 -> f16 convert (8 elems/thread) ----------------------
__global__ __launch_bounds__(256)
void cvt_h_kernel(const float* __restrict__ src, __half* __restrict__ dst, int n)
{
    const int i8 = (blockIdx.x * 256 + threadIdx.x) * 8;
    if (i8 >= n) return;
    const float4 a = *(const float4*)(src + i8);
    const float4 b = *(const float4*)(src + i8 + 4);
    uint4 u;
    u.x = packh(a.x, a.y); u.y = packh(a.z, a.w);
    u.z = packh(b.x, b.y); u.w = packh(b.z, b.w);
    *(uint4*)(dst + i8) = u;
}

// ================= fp16 GEMM, cp.async double-buffered (R7-proven) =========
#define GNC (Cd / 64)
#define GSMB 65536

__device__ __forceinline__ void gemm_stage(const __half* __restrict__ Ab,
                                           const __half* __restrict__ Wb,
                                           uint32_t sb, int buf, int tid)
{
    const uint32_t ab = sb + (buf ? 16384u : 0u);
    const uint32_t bb = sb + 32768u + (buf ? 16384u : 0u);
    #pragma unroll
    for (int p = 0; p < 4; p++) {
        const int s = tid + p * 256;
        const int row = s >> 3, seg = s & 7;
        CP16(ab + SWZ(row * 128 + seg * 16), Ab + (size_t)row * Cd + seg * 8);
    }
    #pragma unroll
    for (int p = 0; p < 4; p++) {
        const int s = tid + p * 256;
        const int row = s >> 3, seg = s & 7;
        CP16(bb + SWZ(row * 128 + seg * 16), Wb + (size_t)row * Cd + seg * 8);
    }
}

template <class Epi>
__device__ __forceinline__ void gemm_h2_body(const __half* __restrict__ A,
                                             const __half* __restrict__ W,
                                             int m0, int n0, const Epi& epi)
{
    extern __shared__ char smc[];
    const uint32_t sb = smem_u32(smc);

    const int tid = threadIdx.x, lane = tid & 31, warp = tid >> 5;
    const int wm = warp >> 2, wn = warp & 3;
    const int gid = lane >> 2, tig = lane & 3;

    const int a_row = (lane & 15);
    const int a_bc  = (lane >> 4) << 4;
    const int b_row = (lane & 7) + ((lane >> 4) << 3);
    const int b_bc  = ((lane >> 3) & 1) << 4;

    float acc[4][4][4];
    #pragma unroll
    for (int i = 0; i < 4; i++)
        #pragma unroll
        for (int j = 0; j < 4; j++)
            #pragma unroll
            for (int r = 0; r < 4; r++) acc[i][j][r] = 0.f;

    const __half* Abase = A + (size_t)m0 * Cd;
    const __half* Wbase = W + (size_t)n0 * Cd;

    gemm_stage(Abase, Wbase, sb, 0, tid);
    CP_COMMIT();
    gemm_stage(Abase + 64, Wbase + 64, sb, 1, tid);
    CP_COMMIT();

    for (int c = 0; c < GNC; c++) {
        const int buf = c & 1;
        CP_WAIT1();
        __syncthreads();

        const uint32_t ab = sb + (buf ? 16384u : 0u);
        const uint32_t bb = sb + 32768u + (buf ? 16384u : 0u);
        #pragma unroll
        for (int ks = 0; ks < 4; ks++) {
            uint32_t a[4][4], bk[2][4];
            #pragma unroll
            for (int mi = 0; mi < 4; mi++) {
                const int row = wm * 64 + mi * 16 + a_row;
                LDM_X4(a[mi][0], a[mi][1], a[mi][2], a[mi][3],
                       ab + SWZ(row * 128 + ks * 32 + a_bc));
            }
            #pragma unroll
            for (int nh = 0; nh < 2; nh++) {
                const int row = wn * 32 + nh * 16 + b_row;
                LDM_X4(bk[nh][0], bk[nh][1], bk[nh][2], bk[nh][3],
                       bb + SWZ(row * 128 + ks * 32 + b_bc));
            }
            #pragma unroll
            for (int mi = 0; mi < 4; mi++)
                #pragma unroll
                for (int ni = 0; ni < 4; ni++)
                    mmah(acc[mi][ni], a[mi][0], a[mi][1], a[mi][2], a[mi][3],
                         bk[ni >> 1][(ni & 1) * 2], bk[ni >> 1][(ni & 1) * 2 + 1]);
        }
        __syncthreads();

        if (c + 2 < GNC)
            gemm_stage(Abase + (c + 2) * 64, Wbase + (c + 2) * 64, sb, buf, tid);
        CP_COMMIT();
    }

    #pragma unroll
    for (int mi = 0; mi < 4; mi++)
        #pragma unroll
        for (int ni = 0; ni < 4; ni++)
            epi.emit(wm * 64 + mi * 16 + gid, wn * 32 + ni * 8 + 2 * tig, acc[mi][ni]);
}

struct EpiQKV {
    __half* outb; const float* bias; int m0, n0; float mult;
    __device__ __forceinline__ void emit(int rl, int cl, const float* a) const {
        const int col = n0 + cl;
        const float b0v = bias[col], b1v = bias[col + 1];
        const int h = col >> 6, hd = col & 63;
        #pragma unroll
        for (int hh = 0; hh < 2; hh++) {
            const int r = m0 + rl + hh * 8;
            const int bb = r >> 11, n = r & 2047;
            const size_t idx = (((size_t)(bb * Hd + h)) * Nd + n) * HDd + hd;
            *(uint32_t*)&outb[idx] = packh((a[hh * 2 + 0] + b0v) * mult,
                                           (a[hh * 2 + 1] + b1v) * mult);
        }
    }
};

struct EpiO {
    float* outp; const float* bias; int m0, n0;
    __device__ __forceinline__ void emit(int rl, int cl, const float* a) const {
        const int col = n0 + cl;
        const float b0v = bias[col], b1v = bias[col + 1];
        #pragma unroll
        for (int hh = 0; hh < 2; hh++) {
            const int r = m0 + rl + hh * 8;
            float2 v;
            v.x = a[hh * 2 + 0] + b0v;
            v.y = a[hh * 2 + 1] + b1v;
            *(float2*)&outp[(size_t)r * Cd + col] = v;
        }
    }
};

__global__ __launch_bounds__(256)
void gemm_qkv_h2(const float* __restrict__ bq, const float* __restrict__ bk,
                 const float* __restrict__ bv)
{
    const int z = blockIdx.z;
    const float* bias = (z == 0) ? bq : (z == 1) ? bk : bv;
    __half* outb      = (z == 0) ? g_qh : (z == 1) ? g_kh : g_vh;
    EpiQKV e{outb, bias, (int)blockIdx.y * 128, (int)blockIdx.x * 128,
             (z == 0) ? SCALEf : 1.0f};
    gemm_h2_body(g_xh, g_wh[z], e.m0, e.n0, e);
}

__global__ __launch_bounds__(256)
void gemm_o_h2(const float* __restrict__ bias, float* __restrict__ out)
{
    EpiO e{out, bias, (int)blockIdx.y * 128, (int)blockIdx.x * 128};
    gemm_h2_body(g_aoh, g_wh[3], e.m0, e.n0, e);
}

// ================= attention: FA2-style register-resident P ================
// 8 warps; warp w owns q rows [w*16, w*16+16) x ALL 64 keys of each chunk.
// S accumulator fragments re-packed in-register as A operands of P@V.
// smem: Q 16KB @0; K ring 3x8KB @16384; V ring 3x8KB @40960; SZ 3x256B @65536.
#define AQS 0
#define AKS 16384
#define AVS 40960
#define ASZ 65536
#define ASMB 66304
#define ANC (Nd / 64)

__global__ __launch_bounds__(256)
void attn_fa2(const float* __restrict__ size)
{
    extern __shared__ char smc[];
    const uint32_t sb = smem_u32(smc);

    const int bh = blockIdx.x;
    const int b = bh / Hd, h = bh % Hd;
    const int q0 = blockIdx.y * 128;
    const int tid = threadIdx.x, lane = tid & 31, warp = tid >> 5;
    const int gid = lane >> 2, tig = lane & 3;

    const __half* qb  = g_qh + ((size_t)bh * Nd + q0) * HDd;
    const __half* kbb = g_kh + (size_t)bh * Nd * HDd;
    const __half* vbb = g_vh + (size_t)bh * Nd * HDd;
    const float* sbase = size + (size_t)b * Nd;

    auto stage_kv = [&](int c, int slot) {
        const __half* Kb = kbb + (size_t)c * 64 * HDd;
        const __half* Vb = vbb + (size_t)c * 64 * HDd;
        const uint32_t kdst = sb + AKS + slot * 8192;
        const uint32_t vdst = sb + AVS + slot * 8192;
        #pragma unroll
        for (int p = 0; p < 2; p++) {
            const int s = tid + p * 256;
            const int row = s >> 3, seg = s & 7;
            CP16(kdst + SWZ(row * 128 + seg * 16), Kb + (size_t)row * HDd + seg * 8);
        }
        #pragma unroll
        for (int p = 0; p < 2; p++) {
            const int s = tid + p * 256;
            const int row = s >> 3, seg = s & 7;
            CP16(vdst + SWZ(row * 128 + seg * 16), Vb + (size_t)row * HDd + seg * 8);
        }
        if (tid < 16)
            CP16(sb + ASZ + slot * 256 + tid * 16, sbase + c * 64 + tid * 4);
    };

    // prologue: Q + chunk0 (group0); chunk1 (group1)
    #pragma unroll
    for (int p = 0; p < 4; p++) {
        const int s = tid + p * 256;
        const int row = s >> 3, seg = s & 7;
        CP16(sb + AQS + SWZ(row * 128 + seg * 16), qb + (size_t)row * HDd + seg * 8);
    }
    stage_kv(0, 0);
    CP_COMMIT();
    stage_kv(1, 1);
    CP_COMMIT();

    // ldmatrix lane addressing
    const int a_row = (lane & 15);
    const int a_bc  = (lane >> 4) << 4;
    const int b_row = (lane & 7) + ((lane >> 4) << 3);
    const int b_bc  = ((lane >> 3) & 1) << 4;
    const int v_row = (lane & 7) + (((lane >> 3) & 1) << 3);
    const int v_bc  = (lane >> 4) << 4;

    // wait for Q + chunk0, then load Q fragments ONCE (held all chunks)
    CP_WAIT1();
    __syncthreads();
    uint32_t qf[4][4];
    #pragma unroll
    for (int ks = 0; ks < 4; ks++) {
        const int row = warp * 16 + a_row;
        LDM_X4(qf[ks][0], qf[ks][1], qf[ks][2], qf[ks][3],
               sb + AQS + SWZ(row * 128 + ks * 32 + a_bc));
    }

    float acc[8][4];
    #pragma unroll
    for (int i = 0; i < 8; i++)
        #pragma unroll
        for (int r = 0; r < 4; r++) acc[i][r] = 0.f;
    float lsum0 = 0.f, lsum1 = 0.f;

    for (int c = 0; c < ANC; c++) {
        const int slot = c % 3;
        if (c > 0) { CP_WAIT1(); __syncthreads(); }

        if (c + 2 < ANC) stage_kv(c + 2, (c + 2) % 3);
        CP_COMMIT();

        const uint32_t kbase = sb + AKS + slot * 8192;
        const uint32_t vbase = sb + AVS + slot * 8192;
        const uint32_t szb   = sb + ASZ + slot * 256;

        // ---- S = Q @ K^T : 16 q-rows x 64 keys (8 n8 tiles) ----
        float sc[8][4];
        #pragma unroll
        for (int i = 0; i < 8; i++)
            #pragma unroll
            for (int r = 0; r < 4; r++) sc[i][r] = 0.f;

        #pragma unroll
        for (int ks = 0; ks < 4; ks++) {
            uint32_t bk[4][4];
            #pragma unroll
            for (int nh = 0; nh < 4; nh++) {
                const int row = nh * 16 + b_row;
                LDM_X4(bk[nh][0], bk[nh][1], bk[nh][2], bk[nh][3],
                       kbase + SWZ(row * 128 + ks * 32 + b_bc));
            }
            #pragma unroll
            for (int nt = 0; nt < 8; nt++)
                mmah(sc[nt], qf[ks][0], qf[ks][1], qf[ks][2], qf[ks][3],
                     bk[nt >> 1][(nt & 1) * 2], bk[nt >> 1][(nt & 1) * 2 + 1]);
        }

        // ---- p = size*exp(s): pack S fragments directly into A operands ----
        uint32_t af[4][4];     // af[kt] covers keys kt*16..kt*16+15
        #pragma unroll
        for (int nt = 0; nt < 8; nt++) {
            const int col = nt * 8 + 2 * tig;
            float szv0, szv1;
            asm volatile("ld.shared.v2.f32 {%0,%1}, [%2];"
                         : "=f"(szv0), "=f"(szv1) : "r"(szb + col * 4));
            const float p0 = szv0 * __expf(sc[nt][0]);
            const float p1 = szv1 * __expf(sc[nt][1]);
            const float p2 = szv0 * __expf(sc[nt][2]);
            const float p3 = szv1 * __expf(sc[nt][3]);
            lsum0 += p0 + p1;
            lsum1 += p2 + p3;
            af[nt >> 1][(nt & 1) * 2 + 0] = packh(p0, p1);
            af[nt >> 1][(nt & 1) * 2 + 1] = packh(p2, p3);
        }

        // ---- O += P @ V ----
        #pragma unroll
        for (int kt = 0; kt < 4; kt++) {
            uint32_t bv[4][4];
            #pragma unroll
            for (int dh = 0; dh < 4; dh++) {
                const int row = kt * 16 + v_row;
                LDM_X4T(bv[dh][0], bv[dh][1], bv[dh][2], bv[dh][3],
                        vbase + SWZ(row * 128 + dh * 32 + v_bc));
            }
            #pragma unroll
            for (int dt = 0; dt < 8; dt++)
                mmah(acc[dt], af[kt][0], af[kt][1], af[kt][2], af[kt][3],
                     bv[dt >> 1][(dt & 1) * 2], bv[dt >> 1][(dt & 1) * 2 + 1]);
        }
    }

    // ---- reduce l within quad (each warp owns its full rows) ----
    lsum0 += __shfl_xor_sync(0xFFFFFFFFu, lsum0, 1);
    lsum0 += __shfl_xor_sync(0xFFFFFFFFu, lsum0, 2);
    lsum1 += __shfl_xor_sync(0xFFFFFFFFu, lsum1, 1);
    lsum1 += __shfl_xor_sync(0xFFFFFFFFu, lsum1, 2);
    const float linv0 = 1.f / lsum0;
    const float linv1 = 1.f / lsum1;

    // ---- normalize and write fp16 g_aoh ----
    const int r0 = q0 + warp * 16 + gid;
    #pragma unroll
    for (int dt = 0; dt < 8; dt++) {
        const int col = dt * 8 + 2 * tig;
        const size_t o0 = ((size_t)(b * Nd + r0)) * Cd + h * HDd + col;
        const size_t o1 = ((size_t)(b * Nd + r0 + 8)) * Cd + h * HDd + col;
        *(uint32_t*)&g_aoh[o0] = packh(acc[dt][0] * linv0, acc[dt][1] * linv0);
        *(uint32_t*)&g_aoh[o1] = packh(acc[dt][2] * linv1, acc[dt][3] * linv1);
    }
}

// ---------------- k mean over heads (from fp16 k) ---------------------------
__global__ __launch_bounds__(256)
void kmean_kernel(float* __restrict__ out)
{
    const int idx = blockIdx.x * 256 + threadIdx.x;
    if (idx >= Bd * Nd * HDd) return;
    const int hd = idx & 63;
    const int n  = (idx >> 6) & 2047;
    const int b  = idx >> 17;
    float s = 0.f;
    #pragma unroll
    for (int h = 0; h < Hd; h++)
        s += __half2float(g_kh[(((size_t)(b * Hd + h)) * Nd + n) * HDd + hd]);
    out[idx] = s * (1.0f / Hd);
}

// ---------------- launch ----------------------------------------------------
extern "C" void kernel_launch(void* const* d_in, const int* in_sizes, int n_in,
                              void* d_out, int out_size)
{
    const float* x    = (const float*)d_in[0];
    const float* size = (const float*)d_in[1];
    const float* q_w  = (const float*)d_in[2];
    const float* q_b  = (const float*)d_in[3];
    const float* k_w  = (const float*)d_in[4];
    const float* k_b  = (const float*)d_in[5];
    const float* v_w  = (const float*)d_in[6];
    const float* v_b  = (const float*)d_in[7];
    const float* o_w  = (const float*)d_in[8];
    const float* o_b  = (const float*)d_in[9];

    float* out   = (float*)d_out;
    float* kmean = out + (size_t)Bd * Nd * Cd;

    cudaFuncSetAttribute(attn_fa2, cudaFuncAttributeMaxDynamicSharedMemorySize, ASMB);
    cudaFuncSetAttribute(gemm_qkv_h2, cudaFuncAttributeMaxDynamicSharedMemorySize, GSMB);
    cudaFuncSetAttribute(gemm_o_h2, cudaFuncAttributeMaxDynamicSharedMemorySize, GSMB);

    __half* xh_p;  cudaGetSymbolAddress((void**)&xh_p, g_xh);
    __half* wh_p;  cudaGetSymbolAddress((void**)&wh_p, g_wh);

    const int nx = Bd * Nd * Cd;
    const int nw = Cd * Cd;
    cvt_h_kernel<<<(nx / 8 + 255) / 256, 256>>>(x, xh_p, nx);
    cvt_h_kernel<<<(nw / 8 + 255) / 256, 256>>>(q_w, wh_p + 0 * (size_t)nw, nw);
    cvt_h_kernel<<<(nw / 8 + 255) / 256, 256>>>(k_w, wh_p + 1 * (size_t)nw, nw);
    cvt_h_kernel<<<(nw / 8 + 255) / 256, 256>>>(v_w, wh_p + 2 * (size_t)nw, nw);
    cvt_h_kernel<<<(nw / 8 + 255) / 256, 256>>>(o_w, wh_p + 3 * (size_t)nw, nw);

    dim3 gqkv(Cd / 128, (Bd * Nd) / 128, 3);
    gemm_qkv_h2<<<gqkv, 256, GSMB>>>(q_b, k_b, v_b);

    kmean_kernel<<<(Bd * Nd * HDd + 255) / 256, 256>>>(kmean);

    dim3 gat(Bd * Hd, Nd / 128);
    attn_fa2<<<gat, 256, ASMB>>>(size);

    dim3 go(Cd / 128, (Bd * Nd) / 128, 1);
    gemm_o_h2<<<go, 256, GSMB>>>(o_b, out);
}

// round 9
// speedup vs baseline: 9.9680x; 1.0920x over previous
#include <cuda_runtime.h>
#include <cuda_fp16.h>
#include <math.h>
#include <cstdint>

#define Bd 8
#define Nd 2048
#define Cd 768
#define Hd 12
#define HDd 64
#define SCALEf 0.125f

// ---------------- scratch ----------------
__device__ __half g_xh[Bd * Nd * Cd];          // fp16 x
__device__ __half g_wh[4][Cd * Cd];            // fp16 weights q,k,v,o
__device__ __half g_qh[Bd * Hd * Nd * HDd];    // fp16, pre-scaled by 0.125
__device__ __half g_kh[Bd * Hd * Nd * HDd];
__device__ __half g_vh[Bd * Hd * Nd * HDd];
__device__ __half g_aoh[Bd * Nd * Cd];         // fp16 attention output

// ---------------- helpers ----------------
__device__ __forceinline__ uint32_t smem_u32(const void* p) {
    uint32_t a;
    asm("{ .reg .u64 t; cvta.to.shared.u64 t, %1; cvt.u32.u64 %0, t; }"
        : "=r"(a) : "l"(p));
    return a;
}

__device__ __forceinline__ void mmah(float* c,
                                     unsigned a0, unsigned a1, unsigned a2, unsigned a3,
                                     unsigned b0, unsigned b1) {
    asm volatile(
        "mma.sync.aligned.m16n8k16.row.col.f32.f16.f16.f32 "
        "{%0,%1,%2,%3}, {%4,%5,%6,%7}, {%8,%9}, {%0,%1,%2,%3};"
        : "+f"(c[0]), "+f"(c[1]), "+f"(c[2]), "+f"(c[3])
        : "r"(a0), "r"(a1), "r"(a2), "r"(a3), "r"(b0), "r"(b1));
}

#define LDM_X4(r0, r1, r2, r3, addr) \
    asm volatile("ldmatrix.sync.aligned.m8n8.x4.shared.b16 {%0,%1,%2,%3}, [%4];" \
                 : "=r"(r0), "=r"(r1), "=r"(r2), "=r"(r3) : "r"(addr))

#define LDM_X4T(r0, r1, r2, r3, addr) \
    asm volatile("ldmatrix.sync.aligned.m8n8.x4.trans.shared.b16 {%0,%1,%2,%3}, [%4];" \
                 : "=r"(r0), "=r"(r1), "=r"(r2), "=r"(r3) : "r"(addr))

#define SWZ(x) ((x) ^ (((x) >> 3) & 0x70))

#define CP16(dst, src) \
    asm volatile("cp.async.cg.shared.global [%0], [%1], 16;" \
                 :: "r"(dst), "l"(src) : "memory")
#define CP_COMMIT() asm volatile("cp.async.commit_group;" ::: "memory")
#define CP_WAIT1() asm volatile("cp.async.wait_group 1;" ::: "memory")

__device__ __forceinline__ uint32_t packh(float a, float b) {
    __half2 t = __floats2half2_rn(a, b);
    return *reinterpret_cast<uint32_t*>(&t);
}

// ---------------- fused f32 -> f16 convert (x + 4 weights) -----------------
#define NX (Bd * Nd * Cd)
#define NW (Cd * Cd)

__global__ __launch_bounds__(256)
void cvt_all_kernel(const float* __restrict__ x,
                    const float* __restrict__ w0, const float* __restrict__ w1,
                    const float* __restrict__ w2, const float* __restrict__ w3,
                    __half* __restrict__ xh, __half* __restrict__ wh)
{
    const long long i8 = (long long)(blockIdx.x * 256 + threadIdx.x) * 8;
    const float* src;
    __half* dst;
    long long off;
    if (i8 < NX) { src = x; dst = xh; off = i8; }
    else {
        const long long j = i8 - NX;
        const int w = (int)(j / NW);
        off = j - (long long)w * NW;
        src = (w == 0) ? w0 : (w == 1) ? w1 : (w == 2) ? w2 : w3;
        dst = wh + (long long)w * NW;
    }
    const float4 a = *(const float4*)(src + off);
    const float4 b = *(const float4*)(src + off + 4);
    uint4 u;
    u.x = packh(a.x, a.y); u.y = packh(a.z, a.w);
    u.z = packh(b.x, b.y); u.w = packh(b.z, b.w);
    *(uint4*)(dst + off) = u;
}

// ================= fp16 GEMM, cp.async double-buffered (R7-proven) =========
#define GNC (Cd / 64)
#define GSMB 65536

__device__ __forceinline__ void gemm_stage(const __half* __restrict__ Ab,
                                           const __half* __restrict__ Wb,
                                           uint32_t sb, int buf, int tid)
{
    const uint32_t ab = sb + (buf ? 16384u : 0u);
    const uint32_t bb = sb + 32768u + (buf ? 16384u : 0u);
    #pragma unroll
    for (int p = 0; p < 4; p++) {
        const int s = tid + p * 256;
        const int row = s >> 3, seg = s & 7;
        CP16(ab + SWZ(row * 128 + seg * 16), Ab + (size_t)row * Cd + seg * 8);
    }
    #pragma unroll
    for (int p = 0; p < 4; p++) {
        const int s = tid + p * 256;
        const int row = s >> 3, seg = s & 7;
        CP16(bb + SWZ(row * 128 + seg * 16), Wb + (size_t)row * Cd + seg * 8);
    }
}

template <class Epi>
__device__ __forceinline__ void gemm_h2_body(const __half* __restrict__ A,
                                             const __half* __restrict__ W,
                                             int m0, int n0, const Epi& epi)
{
    extern __shared__ char smc[];
    const uint32_t sb = smem_u32(smc);

    const int tid = threadIdx.x, lane = tid & 31, warp = tid >> 5;
    const int wm = warp >> 2, wn = warp & 3;
    const int gid = lane >> 2, tig = lane & 3;

    const int a_row = (lane & 15);
    const int a_bc  = (lane >> 4) << 4;
    const int b_row = (lane & 7) + ((lane >> 4) << 3);
    const int b_bc  = ((lane >> 3) & 1) << 4;

    float acc[4][4][4];
    #pragma unroll
    for (int i = 0; i < 4; i++)
        #pragma unroll
        for (int j = 0; j < 4; j++)
            #pragma unroll
            for (int r = 0; r < 4; r++) acc[i][j][r] = 0.f;

    const __half* Abase = A + (size_t)m0 * Cd;
    const __half* Wbase = W + (size_t)n0 * Cd;

    gemm_stage(Abase, Wbase, sb, 0, tid);
    CP_COMMIT();
    gemm_stage(Abase + 64, Wbase + 64, sb, 1, tid);
    CP_COMMIT();

    for (int c = 0; c < GNC; c++) {
        const int buf = c & 1;
        CP_WAIT1();
        __syncthreads();

        const uint32_t ab = sb + (buf ? 16384u : 0u);
        const uint32_t bb = sb + 32768u + (buf ? 16384u : 0u);
        #pragma unroll
        for (int ks = 0; ks < 4; ks++) {
            uint32_t a[4][4], bk[2][4];
            #pragma unroll
            for (int mi = 0; mi < 4; mi++) {
                const int row = wm * 64 + mi * 16 + a_row;
                LDM_X4(a[mi][0], a[mi][1], a[mi][2], a[mi][3],
                       ab + SWZ(row * 128 + ks * 32 + a_bc));
            }
            #pragma unroll
            for (int nh = 0; nh < 2; nh++) {
                const int row = wn * 32 + nh * 16 + b_row;
                LDM_X4(bk[nh][0], bk[nh][1], bk[nh][2], bk[nh][3],
                       bb + SWZ(row * 128 + ks * 32 + b_bc));
            }
            #pragma unroll
            for (int mi = 0; mi < 4; mi++)
                #pragma unroll
                for (int ni = 0; ni < 4; ni++)
                    mmah(acc[mi][ni], a[mi][0], a[mi][1], a[mi][2], a[mi][3],
                         bk[ni >> 1][(ni & 1) * 2], bk[ni >> 1][(ni & 1) * 2 + 1]);
        }
        __syncthreads();

        if (c + 2 < GNC)
            gemm_stage(Abase + (c + 2) * 64, Wbase + (c + 2) * 64, sb, buf, tid);
        CP_COMMIT();
    }

    #pragma unroll
    for (int mi = 0; mi < 4; mi++)
        #pragma unroll
        for (int ni = 0; ni < 4; ni++)
            epi.emit(wm * 64 + mi * 16 + gid, wn * 32 + ni * 8 + 2 * tig, acc[mi][ni]);
}

struct EpiQKV {
    __half* outb; const float* bias; int m0, n0; float mult;
    __device__ __forceinline__ void emit(int rl, int cl, const float* a) const {
        const int col = n0 + cl;
        const float b0v = bias[col], b1v = bias[col + 1];
        const int h = col >> 6, hd = col & 63;
        #pragma unroll
        for (int hh = 0; hh < 2; hh++) {
            const int r = m0 + rl + hh * 8;
            const int bb = r >> 11, n = r & 2047;
            const size_t idx = (((size_t)(bb * Hd + h)) * Nd + n) * HDd + hd;
            *(uint32_t*)&outb[idx] = packh((a[hh * 2 + 0] + b0v) * mult,
                                           (a[hh * 2 + 1] + b1v) * mult);
        }
    }
};

struct EpiO {
    float* outp; const float* bias; int m0, n0;
    __device__ __forceinline__ void emit(int rl, int cl, const float* a) const {
        const int col = n0 + cl;
        const float b0v = bias[col], b1v = bias[col + 1];
        #pragma unroll
        for (int hh = 0; hh < 2; hh++) {
            const int r = m0 + rl + hh * 8;
            float2 v;
            v.x = a[hh * 2 + 0] + b0v;
            v.y = a[hh * 2 + 1] + b1v;
            *(float2*)&outp[(size_t)r * Cd + col] = v;
        }
    }
};

__global__ __launch_bounds__(256)
void gemm_qkv_h2(const float* __restrict__ bq, const float* __restrict__ bk,
                 const float* __restrict__ bv)
{
    const int z = blockIdx.z;
    const float* bias = (z == 0) ? bq : (z == 1) ? bk : bv;
    __half* outb      = (z == 0) ? g_qh : (z == 1) ? g_kh : g_vh;
    EpiQKV e{outb, bias, (int)blockIdx.y * 128, (int)blockIdx.x * 128,
             (z == 0) ? SCALEf : 1.0f};
    gemm_h2_body(g_xh, g_wh[z], e.m0, e.n0, e);
}

__global__ __launch_bounds__(256)
void gemm_o_h2(const float* __restrict__ bias, float* __restrict__ out)
{
    EpiO e{out, bias, (int)blockIdx.y * 128, (int)blockIdx.x * 128};
    gemm_h2_body(g_aoh, g_wh[3], e.m0, e.n0, e);
}

// ================= attention: FA2 register-P, 2 CTAs/SM ====================
// 8 warps; warp w owns q rows [w*16, w*16+16) x ALL 64 keys of each chunk.
// S computed in two n-groups of 4 n8-tiles to keep live regs under 128.
// smem: Q 16KB @0; K ring 3x8KB @16384; V ring 3x8KB @40960; SZ 3x256B @65536.
#define AQS 0
#define AKS 16384
#define AVS 40960
#define ASZ 65536
#define ASMB 66304
#define ANC (Nd / 64)

__global__ __launch_bounds__(256, 2)
void attn_fa2(const float* __restrict__ size)
{
    extern __shared__ char smc[];
    const uint32_t sb = smem_u32(smc);

    const int bh = blockIdx.x;
    const int b = bh / Hd, h = bh % Hd;
    const int q0 = blockIdx.y * 128;
    const int tid = threadIdx.x, lane = tid & 31, warp = tid >> 5;
    const int gid = lane >> 2, tig = lane & 3;

    const __half* qb  = g_qh + ((size_t)bh * Nd + q0) * HDd;
    const __half* kbb = g_kh + (size_t)bh * Nd * HDd;
    const __half* vbb = g_vh + (size_t)bh * Nd * HDd;
    const float* sbase = size + (size_t)b * Nd;

    auto stage_kv = [&](int c, int slot) {
        const __half* Kb = kbb + (size_t)c * 64 * HDd;
        const __half* Vb = vbb + (size_t)c * 64 * HDd;
        const uint32_t kdst = sb + AKS + slot * 8192;
        const uint32_t vdst = sb + AVS + slot * 8192;
        #pragma unroll
        for (int p = 0; p < 2; p++) {
            const int s = tid + p * 256;
            const int row = s >> 3, seg = s & 7;
            CP16(kdst + SWZ(row * 128 + seg * 16), Kb + (size_t)row * HDd + seg * 8);
        }
        #pragma unroll
        for (int p = 0; p < 2; p++) {
            const int s = tid + p * 256;
            const int row = s >> 3, seg = s & 7;
            CP16(vdst + SWZ(row * 128 + seg * 16), Vb + (size_t)row * HDd + seg * 8);
        }
        if (tid < 16)
            CP16(sb + ASZ + slot * 256 + tid * 16, sbase + c * 64 + tid * 4);
    };

    // prologue: Q + chunk0 (group0); chunk1 (group1)
    #pragma unroll
    for (int p = 0; p < 4; p++) {
        const int s = tid + p * 256;
        const int row = s >> 3, seg = s & 7;
        CP16(sb + AQS + SWZ(row * 128 + seg * 16), qb + (size_t)row * HDd + seg * 8);
    }
    stage_kv(0, 0);
    CP_COMMIT();
    stage_kv(1, 1);
    CP_COMMIT();

    const int a_row = (lane & 15);
    const int a_bc  = (lane >> 4) << 4;
    const int b_row = (lane & 7) + ((lane >> 4) << 3);
    const int b_bc  = ((lane >> 3) & 1) << 4;
    const int v_row = (lane & 7) + (((lane >> 3) & 1) << 3);
    const int v_bc  = (lane >> 4) << 4;

    // wait for Q + chunk0, load Q fragments ONCE
    CP_WAIT1();
    __syncthreads();
    uint32_t qf[4][4];
    #pragma unroll
    for (int ks = 0; ks < 4; ks++) {
        const int row = warp * 16 + a_row;
        LDM_X4(qf[ks][0], qf[ks][1], qf[ks][2], qf[ks][3],
               sb + AQS + SWZ(row * 128 + ks * 32 + a_bc));
    }

    float acc[8][4];
    #pragma unroll
    for (int i = 0; i < 8; i++)
        #pragma unroll
        for (int r = 0; r < 4; r++) acc[i][r] = 0.f;
    float lsum0 = 0.f, lsum1 = 0.f;

    for (int c = 0; c < ANC; c++) {
        const int slot = c % 3;
        if (c > 0) { CP_WAIT1(); __syncthreads(); }

        if (c + 2 < ANC) stage_kv(c + 2, (c + 2) % 3);
        CP_COMMIT();

        const uint32_t kbase = sb + AKS + slot * 8192;
        const uint32_t vbase = sb + AVS + slot * 8192;
        const uint32_t szb   = sb + ASZ + slot * 256;

        // ---- S = Q @ K^T in two n-groups; exp/pack per group ----
        uint32_t af[4][4];     // af[kt] covers keys kt*16..kt*16+15
        #pragma unroll
        for (int g = 0; g < 2; g++) {
            float sc4[4][4];
            #pragma unroll
            for (int i = 0; i < 4; i++)
                #pragma unroll
                for (int r = 0; r < 4; r++) sc4[i][r] = 0.f;

            #pragma unroll
            for (int ks = 0; ks < 4; ks++) {
                uint32_t bk[2][4];
                #pragma unroll
                for (int nh = 0; nh < 2; nh++) {
                    const int row = (g * 2 + nh) * 16 + b_row;
                    LDM_X4(bk[nh][0], bk[nh][1], bk[nh][2], bk[nh][3],
                           kbase + SWZ(row * 128 + ks * 32 + b_bc));
                }
                #pragma unroll
                for (int nt = 0; nt < 4; nt++)
                    mmah(sc4[nt], qf[ks][0], qf[ks][1], qf[ks][2], qf[ks][3],
                         bk[nt >> 1][(nt & 1) * 2], bk[nt >> 1][(nt & 1) * 2 + 1]);
            }

            #pragma unroll
            for (int nt = 0; nt < 4; nt++) {
                const int col = (g * 4 + nt) * 8 + 2 * tig;
                float szv0, szv1;
                asm volatile("ld.shared.v2.f32 {%0,%1}, [%2];"
                             : "=f"(szv0), "=f"(szv1) : "r"(szb + col * 4));
                const float p0 = szv0 * __expf(sc4[nt][0]);
                const float p1 = szv1 * __expf(sc4[nt][1]);
                const float p2 = szv0 * __expf(sc4[nt][2]);
                const float p3 = szv1 * __expf(sc4[nt][3]);
                lsum0 += p0 + p1;
                lsum1 += p2 + p3;
                af[g * 2 + (nt >> 1)][(nt & 1) * 2 + 0] = packh(p0, p1);
                af[g * 2 + (nt >> 1)][(nt & 1) * 2 + 1] = packh(p2, p3);
            }
        }

        // ---- O += P @ V ----
        #pragma unroll
        for (int kt = 0; kt < 4; kt++) {
            uint32_t bv[4][4];
            #pragma unroll
            for (int dh = 0; dh < 4; dh++) {
                const int row = kt * 16 + v_row;
                LDM_X4T(bv[dh][0], bv[dh][1], bv[dh][2], bv[dh][3],
                        vbase + SWZ(row * 128 + dh * 32 + v_bc));
            }
            #pragma unroll
            for (int dt = 0; dt < 8; dt++)
                mmah(acc[dt], af[kt][0], af[kt][1], af[kt][2], af[kt][3],
                     bv[dt >> 1][(dt & 1) * 2], bv[dt >> 1][(dt & 1) * 2 + 1]);
        }
    }

    // ---- reduce l within quad; normalize; write fp16 g_aoh ----
    lsum0 += __shfl_xor_sync(0xFFFFFFFFu, lsum0, 1);
    lsum0 += __shfl_xor_sync(0xFFFFFFFFu, lsum0, 2);
    lsum1 += __shfl_xor_sync(0xFFFFFFFFu, lsum1, 1);
    lsum1 += __shfl_xor_sync(0xFFFFFFFFu, lsum1, 2);
    const float linv0 = 1.f / lsum0;
    const float linv1 = 1.f / lsum1;

    const int r0 = q0 + warp * 16 + gid;
    #pragma unroll
    for (int dt = 0; dt < 8; dt++) {
        const int col = dt * 8 + 2 * tig;
        const size_t o0 = ((size_t)(b * Nd + r0)) * Cd + h * HDd + col;
        const size_t o1 = ((size_t)(b * Nd + r0 + 8)) * Cd + h * HDd + col;
        *(uint32_t*)&g_aoh[o0] = packh(acc[dt][0] * linv0, acc[dt][1] * linv0);
        *(uint32_t*)&g_aoh[o1] = packh(acc[dt][2] * linv1, acc[dt][3] * linv1);
    }
}

// ---------------- k mean over heads (half2-vectorized) ----------------------
__global__ __launch_bounds__(256)
void kmean_kernel(float* __restrict__ out)
{
    const int i2 = blockIdx.x * 256 + threadIdx.x;      // over B*N*HD/2
    if (i2 >= Bd * Nd * HDd / 2) return;
    const int idx = i2 * 2;
    const int hd = idx & 63;
    const int n  = (idx >> 6) & 2047;
    const int b  = idx >> 17;
    float s0 = 0.f, s1 = 0.f;
    #pragma unroll
    for (int h = 0; h < Hd; h++) {
        const __half2 v = *(const __half2*)&g_kh[(((size_t)(b * Hd + h)) * Nd + n) * HDd + hd];
        const float2 f = __half22float2(v);
        s0 += f.x; s1 += f.y;
    }
    *(float2*)&out[idx] = make_float2(s0 * (1.0f / Hd), s1 * (1.0f / Hd));
}

// ---------------- launch ----------------------------------------------------
extern "C" void kernel_launch(void* const* d_in, const int* in_sizes, int n_in,
                              void* d_out, int out_size)
{
    const float* x    = (const float*)d_in[0];
    const float* size = (const float*)d_in[1];
    const float* q_w  = (const float*)d_in[2];
    const float* q_b  = (const float*)d_in[3];
    const float* k_w  = (const float*)d_in[4];
    const float* k_b  = (const float*)d_in[5];
    const float* v_w  = (const float*)d_in[6];
    const float* v_b  = (const float*)d_in[7];
    const float* o_w  = (const float*)d_in[8];
    const float* o_b  = (const float*)d_in[9];

    float* out   = (float*)d_out;
    float* kmean = out + (size_t)Bd * Nd * Cd;

    cudaFuncSetAttribute(attn_fa2, cudaFuncAttributeMaxDynamicSharedMemorySize, ASMB);
    cudaFuncSetAttribute(gemm_qkv_h2, cudaFuncAttributeMaxDynamicSharedMemorySize, GSMB);
    cudaFuncSetAttribute(gemm_o_h2, cudaFuncAttributeMaxDynamicSharedMemorySize, GSMB);

    __half* xh_p;  cudaGetSymbolAddress((void**)&xh_p, g_xh);
    __half* wh_p;  cudaGetSymbolAddress((void**)&wh_p, g_wh);

    const long long ntot = (long long)NX + 4LL * NW;
    cvt_all_kernel<<<(unsigned)((ntot / 8 + 255) / 256), 256>>>(
        x, q_w, k_w, v_w, o_w, xh_p, wh_p);

    dim3 gqkv(Cd / 128, (Bd * Nd) / 128, 3);
    gemm_qkv_h2<<<gqkv, 256, GSMB>>>(q_b, k_b, v_b);

    kmean_kernel<<<(Bd * Nd * HDd / 2 + 255) / 256, 256>>>(kmean);

    dim3 gat(Bd * Hd, Nd / 128);
    attn_fa2<<<gat, 256, ASMB>>>(size);

    dim3 go(Cd / 128, (Bd * Nd) / 128, 1);
    gemm_o_h2<<<go, 256, GSMB>>>(o_b, out);
}

// round 10
// speedup vs baseline: 10.6084x; 1.0642x over previous
#include <cuda_runtime.h>
#include <cuda_fp16.h>
#include <math.h>
#include <cstdint>

#define Bd 8
#define Nd 2048
#define Cd 768
#define Hd 12
#define HDd 64
// q pre-scale folded with log2(e): 0.125 * 1.44269504088896
#define QSCALEf 0.180336880111112f

// ---------------- scratch ----------------
__device__ __half g_xh[Bd * Nd * Cd];          // fp16 x
__device__ __half g_wh[4][Cd * Cd];            // fp16 weights q,k,v,o
__device__ float  g_lsz[Bd * Nd];              // log2(size)
__device__ __half g_qh[Bd * Hd * Nd * HDd];    // fp16, pre-scaled by 0.125*log2e
__device__ __half g_kh[Bd * Hd * Nd * HDd];
__device__ __half g_vh[Bd * Hd * Nd * HDd];
__device__ __half g_aoh[Bd * Nd * Cd];         // fp16 attention output

// ---------------- helpers ----------------
__device__ __forceinline__ uint32_t smem_u32(const void* p) {
    uint32_t a;
    asm("{ .reg .u64 t; cvta.to.shared.u64 t, %1; cvt.u32.u64 %0, t; }"
        : "=r"(a) : "l"(p));
    return a;
}

__device__ __forceinline__ void mmah(float* c,
                                     unsigned a0, unsigned a1, unsigned a2, unsigned a3,
                                     unsigned b0, unsigned b1) {
    asm volatile(
        "mma.sync.aligned.m16n8k16.row.col.f32.f16.f16.f32 "
        "{%0,%1,%2,%3}, {%4,%5,%6,%7}, {%8,%9}, {%0,%1,%2,%3};"
        : "+f"(c[0]), "+f"(c[1]), "+f"(c[2]), "+f"(c[3])
        : "r"(a0), "r"(a1), "r"(a2), "r"(a3), "r"(b0), "r"(b1));
}

#define LDM_X4(r0, r1, r2, r3, addr) \
    asm volatile("ldmatrix.sync.aligned.m8n8.x4.shared.b16 {%0,%1,%2,%3}, [%4];" \
                 : "=r"(r0), "=r"(r1), "=r"(r2), "=r"(r3) : "r"(addr))

#define LDM_X4T(r0, r1, r2, r3, addr) \
    asm volatile("ldmatrix.sync.aligned.m8n8.x4.trans.shared.b16 {%0,%1,%2,%3}, [%4];" \
                 : "=r"(r0), "=r"(r1), "=r"(r2), "=r"(r3) : "r"(addr))

#define SWZ(x) ((x) ^ (((x) >> 3) & 0x70))

#define CP16(dst, src) \
    asm volatile("cp.async.cg.shared.global [%0], [%1], 16;" \
                 :: "r"(dst), "l"(src) : "memory")
#define CP_COMMIT() asm volatile("cp.async.commit_group;" ::: "memory")
#define CP_WAIT1() asm volatile("cp.async.wait_group 1;" ::: "memory")

__device__ __forceinline__ uint32_t packh(float a, float b) {
    __half2 t = __floats2half2_rn(a, b);
    return *reinterpret_cast<uint32_t*>(&t);
}

__device__ __forceinline__ float ex2(float x) {
    float r;
    asm("ex2.approx.ftz.f32 %0, %1;" : "=f"(r) : "f"(x));
    return r;
}

__device__ __forceinline__ float lg2(float x) {
    float r;
    asm("lg2.approx.f32 %0, %1;" : "=f"(r) : "f"(x));
    return r;
}

// ---------------- fused f32 -> f16 convert + log2(size) --------------------
#define NX (Bd * Nd * Cd)
#define NW (Cd * Cd)
#define NS (Bd * Nd)

__global__ __launch_bounds__(256)
void cvt_all_kernel(const float* __restrict__ x,
                    const float* __restrict__ w0, const float* __restrict__ w1,
                    const float* __restrict__ w2, const float* __restrict__ w3,
                    const float* __restrict__ size,
                    __half* __restrict__ xh, __half* __restrict__ wh,
                    float* __restrict__ lsz)
{
    const long long i8 = (long long)(blockIdx.x * 256 + threadIdx.x) * 8;
    if (i8 >= (long long)NX + 4LL * NW) {
        const long long off = i8 - NX - 4LL * NW;
        if (off >= NS) return;
        const float4 a = *(const float4*)(size + off);
        const float4 b = *(const float4*)(size + off + 4);
        float4 la, lb4;
        la.x = lg2(a.x); la.y = lg2(a.y); la.z = lg2(a.z); la.w = lg2(a.w);
        lb4.x = lg2(b.x); lb4.y = lg2(b.y); lb4.z = lg2(b.z); lb4.w = lg2(b.w);
        *(float4*)(lsz + off) = la;
        *(float4*)(lsz + off + 4) = lb4;
        return;
    }
    const float* src;
    __half* dst;
    long long off;
    if (i8 < NX) { src = x; dst = xh; off = i8; }
    else {
        const long long j = i8 - NX;
        const int w = (int)(j / NW);
        off = j - (long long)w * NW;
        src = (w == 0) ? w0 : (w == 1) ? w1 : (w == 2) ? w2 : w3;
        dst = wh + (long long)w * NW;
    }
    const float4 a = *(const float4*)(src + off);
    const float4 b = *(const float4*)(src + off + 4);
    uint4 u;
    u.x = packh(a.x, a.y); u.y = packh(a.z, a.w);
    u.z = packh(b.x, b.y); u.w = packh(b.z, b.w);
    *(uint4*)(dst + off) = u;
}

// ================= fp16 GEMM, cp.async double-buffered (R7-proven) =========
#define GNC (Cd / 64)
#define GSMB 65536

__device__ __forceinline__ void gemm_stage(const __half* __restrict__ Ab,
                                           const __half* __restrict__ Wb,
                                           uint32_t sb, int buf, int tid)
{
    const uint32_t ab = sb + (buf ? 16384u : 0u);
    const uint32_t bb = sb + 32768u + (buf ? 16384u : 0u);
    #pragma unroll
    for (int p = 0; p < 4; p++) {
        const int s = tid + p * 256;
        const int row = s >> 3, seg = s & 7;
        CP16(ab + SWZ(row * 128 + seg * 16), Ab + (size_t)row * Cd + seg * 8);
    }
    #pragma unroll
    for (int p = 0; p < 4; p++) {
        const int s = tid + p * 256;
        const int row = s >> 3, seg = s & 7;
        CP16(bb + SWZ(row * 128 + seg * 16), Wb + (size_t)row * Cd + seg * 8);
    }
}

template <class Epi>
__device__ __forceinline__ void gemm_h2_body(const __half* __restrict__ A,
                                             const __half* __restrict__ W,
                                             int m0, int n0, const Epi& epi)
{
    extern __shared__ char smc[];
    const uint32_t sb = smem_u32(smc);

    const int tid = threadIdx.x, lane = tid & 31, warp = tid >> 5;
    const int wm = warp >> 2, wn = warp & 3;
    const int gid = lane >> 2, tig = lane & 3;

    const int a_row = (lane & 15);
    const int a_bc  = (lane >> 4) << 4;
    const int b_row = (lane & 7) + ((lane >> 4) << 3);
    const int b_bc  = ((lane >> 3) & 1) << 4;

    float acc[4][4][4];
    #pragma unroll
    for (int i = 0; i < 4; i++)
        #pragma unroll
        for (int j = 0; j < 4; j++)
            #pragma unroll
            for (int r = 0; r < 4; r++) acc[i][j][r] = 0.f;

    const __half* Abase = A + (size_t)m0 * Cd;
    const __half* Wbase = W + (size_t)n0 * Cd;

    gemm_stage(Abase, Wbase, sb, 0, tid);
    CP_COMMIT();
    gemm_stage(Abase + 64, Wbase + 64, sb, 1, tid);
    CP_COMMIT();

    for (int c = 0; c < GNC; c++) {
        const int buf = c & 1;
        CP_WAIT1();
        __syncthreads();

        const uint32_t ab = sb + (buf ? 16384u : 0u);
        const uint32_t bb = sb + 32768u + (buf ? 16384u : 0u);
        #pragma unroll
        for (int ks = 0; ks < 4; ks++) {
            uint32_t a[4][4], bk[2][4];
            #pragma unroll
            for (int mi = 0; mi < 4; mi++) {
                const int row = wm * 64 + mi * 16 + a_row;
                LDM_X4(a[mi][0], a[mi][1], a[mi][2], a[mi][3],
                       ab + SWZ(row * 128 + ks * 32 + a_bc));
            }
            #pragma unroll
            for (int nh = 0; nh < 2; nh++) {
                const int row = wn * 32 + nh * 16 + b_row;
                LDM_X4(bk[nh][0], bk[nh][1], bk[nh][2], bk[nh][3],
                       bb + SWZ(row * 128 + ks * 32 + b_bc));
            }
            #pragma unroll
            for (int mi = 0; mi < 4; mi++)
                #pragma unroll
                for (int ni = 0; ni < 4; ni++)
                    mmah(acc[mi][ni], a[mi][0], a[mi][1], a[mi][2], a[mi][3],
                         bk[ni >> 1][(ni & 1) * 2], bk[ni >> 1][(ni & 1) * 2 + 1]);
        }
        __syncthreads();

        if (c + 2 < GNC)
            gemm_stage(Abase + (c + 2) * 64, Wbase + (c + 2) * 64, sb, buf, tid);
        CP_COMMIT();
    }

    #pragma unroll
    for (int mi = 0; mi < 4; mi++)
        #pragma unroll
        for (int ni = 0; ni < 4; ni++)
            epi.emit(wm * 64 + mi * 16 + gid, wn * 32 + ni * 8 + 2 * tig, acc[mi][ni]);
}

struct EpiQKV {
    __half* outb; const float* bias; int m0, n0; float mult;
    __device__ __forceinline__ void emit(int rl, int cl, const float* a) const {
        const int col = n0 + cl;
        const float b0v = bias[col], b1v = bias[col + 1];
        const int h = col >> 6, hd = col & 63;
        #pragma unroll
        for (int hh = 0; hh < 2; hh++) {
            const int r = m0 + rl + hh * 8;
            const int bb = r >> 11, n = r & 2047;
            const size_t idx = (((size_t)(bb * Hd + h)) * Nd + n) * HDd + hd;
            *(uint32_t*)&outb[idx] = packh((a[hh * 2 + 0] + b0v) * mult,
                                           (a[hh * 2 + 1] + b1v) * mult);
        }
    }
};

struct EpiO {
    float* outp; const float* bias; int m0, n0;
    __device__ __forceinline__ void emit(int rl, int cl, const float* a) const {
        const int col = n0 + cl;
        const float b0v = bias[col], b1v = bias[col + 1];
        #pragma unroll
        for (int hh = 0; hh < 2; hh++) {
            const int r = m0 + rl + hh * 8;
            float2 v;
            v.x = a[hh * 2 + 0] + b0v;
            v.y = a[hh * 2 + 1] + b1v;
            *(float2*)&outp[(size_t)r * Cd + col] = v;
        }
    }
};

__global__ __launch_bounds__(256)
void gemm_qkv_h2(const float* __restrict__ bq, const float* __restrict__ bk,
                 const float* __restrict__ bv)
{
    const int z = blockIdx.z;
    const float* bias = (z == 0) ? bq : (z == 1) ? bk : bv;
    __half* outb      = (z == 0) ? g_qh : (z == 1) ? g_kh : g_vh;
    EpiQKV e{outb, bias, (int)blockIdx.y * 128, (int)blockIdx.x * 128,
             (z == 0) ? QSCALEf : 1.0f};
    gemm_h2_body(g_xh, g_wh[z], e.m0, e.n0, e);
}

__global__ __launch_bounds__(256)
void gemm_o_h2(const float* __restrict__ bias, float* __restrict__ out)
{
    EpiO e{out, bias, (int)blockIdx.y * 128, (int)blockIdx.x * 128};
    gemm_h2_body(g_aoh, g_wh[3], e.m0, e.n0, e);
}

// ================= attention: FA2 register-P, exp2 softmax, mma-l ==========
// 8 warps; warp w owns q rows [w*16, w*16+16) x ALL 64 keys of each chunk.
// p = exp2(s + log2(size_k)); l accumulated via mma against ones-B fragment.
// smem: Q 16KB @0; K ring 3x8KB @16384; V ring 3x8KB @40960; LB 3x256B @65536.
#define AQS 0
#define AKS 16384
#define AVS 40960
#define ASZ 65536
#define ASMB 66304
#define ANC (Nd / 64)
#define ONESH2 0x3C003C00u

__global__ __launch_bounds__(256, 2)
void attn_fa2(const float* __restrict__ lszp)
{
    extern __shared__ char smc[];
    const uint32_t sb = smem_u32(smc);

    const int bh = blockIdx.x;
    const int b = bh / Hd, h = bh % Hd;
    const int q0 = blockIdx.y * 128;
    const int tid = threadIdx.x, lane = tid & 31, warp = tid >> 5;
    const int gid = lane >> 2, tig = lane & 3;

    const __half* qb  = g_qh + ((size_t)bh * Nd + q0) * HDd;
    const __half* kbb = g_kh + (size_t)bh * Nd * HDd;
    const __half* vbb = g_vh + (size_t)bh * Nd * HDd;
    const float* lbase = lszp + (size_t)b * Nd;

    auto stage_kv = [&](int c, int slot) {
        const __half* Kb = kbb + (size_t)c * 64 * HDd;
        const __half* Vb = vbb + (size_t)c * 64 * HDd;
        const uint32_t kdst = sb + AKS + slot * 8192;
        const uint32_t vdst = sb + AVS + slot * 8192;
        #pragma unroll
        for (int p = 0; p < 2; p++) {
            const int s = tid + p * 256;
            const int row = s >> 3, seg = s & 7;
            CP16(kdst + SWZ(row * 128 + seg * 16), Kb + (size_t)row * HDd + seg * 8);
        }
        #pragma unroll
        for (int p = 0; p < 2; p++) {
            const int s = tid + p * 256;
            const int row = s >> 3, seg = s & 7;
            CP16(vdst + SWZ(row * 128 + seg * 16), Vb + (size_t)row * HDd + seg * 8);
        }
        if (tid < 16)
            CP16(sb + ASZ + slot * 256 + tid * 16, lbase + c * 64 + tid * 4);
    };

    // prologue
    #pragma unroll
    for (int p = 0; p < 4; p++) {
        const int s = tid + p * 256;
        const int row = s >> 3, seg = s & 7;
        CP16(sb + AQS + SWZ(row * 128 + seg * 16), qb + (size_t)row * HDd + seg * 8);
    }
    stage_kv(0, 0);
    CP_COMMIT();
    stage_kv(1, 1);
    CP_COMMIT();

    const int a_row = (lane & 15);
    const int a_bc  = (lane >> 4) << 4;
    const int b_row = (lane & 7) + ((lane >> 4) << 3);
    const int b_bc  = ((lane >> 3) & 1) << 4;
    const int v_row = (lane & 7) + (((lane >> 3) & 1) << 3);
    const int v_bc  = (lane >> 4) << 4;

    CP_WAIT1();
    __syncthreads();
    uint32_t qf[4][4];
    #pragma unroll
    for (int ks = 0; ks < 4; ks++) {
        const int row = warp * 16 + a_row;
        LDM_X4(qf[ks][0], qf[ks][1], qf[ks][2], qf[ks][3],
               sb + AQS + SWZ(row * 128 + ks * 32 + a_bc));
    }

    float acc[8][4];
    #pragma unroll
    for (int i = 0; i < 8; i++)
        #pragma unroll
        for (int r = 0; r < 4; r++) acc[i][r] = 0.f;
    float lacc[4] = {0.f, 0.f, 0.f, 0.f};

    for (int c = 0; c < ANC; c++) {
        const int slot = c % 3;
        if (c > 0) { CP_WAIT1(); __syncthreads(); }

        if (c + 2 < ANC) stage_kv(c + 2, (c + 2) % 3);
        CP_COMMIT();

        const uint32_t kbase = sb + AKS + slot * 8192;
        const uint32_t vbase = sb + AVS + slot * 8192;
        const uint32_t szb   = sb + ASZ + slot * 256;

        // ---- S = Q @ K^T in two n-groups; p = ex2(s + lb) per group ----
        uint32_t af[4][4];     // af[kt] covers keys kt*16..kt*16+15
        #pragma unroll
        for (int g = 0; g < 2; g++) {
            float sc4[4][4];
            #pragma unroll
            for (int i = 0; i < 4; i++)
                #pragma unroll
                for (int r = 0; r < 4; r++) sc4[i][r] = 0.f;

            #pragma unroll
            for (int ks = 0; ks < 4; ks++) {
                uint32_t bk[2][4];
                #pragma unroll
                for (int nh = 0; nh < 2; nh++) {
                    const int row = (g * 2 + nh) * 16 + b_row;
                    LDM_X4(bk[nh][0], bk[nh][1], bk[nh][2], bk[nh][3],
                           kbase + SWZ(row * 128 + ks * 32 + b_bc));
                }
                #pragma unroll
                for (int nt = 0; nt < 4; nt++)
                    mmah(sc4[nt], qf[ks][0], qf[ks][1], qf[ks][2], qf[ks][3],
                         bk[nt >> 1][(nt & 1) * 2], bk[nt >> 1][(nt & 1) * 2 + 1]);
            }

            #pragma unroll
            for (int nt = 0; nt < 4; nt++) {
                const int col = (g * 4 + nt) * 8 + 2 * tig;
                float lb0, lb1;
                asm volatile("ld.shared.v2.f32 {%0,%1}, [%2];"
                             : "=f"(lb0), "=f"(lb1) : "r"(szb + col * 4));
                const float p0 = ex2(sc4[nt][0] + lb0);
                const float p1 = ex2(sc4[nt][1] + lb1);
                const float p2 = ex2(sc4[nt][2] + lb0);
                const float p3 = ex2(sc4[nt][3] + lb1);
                af[g * 2 + (nt >> 1)][(nt & 1) * 2 + 0] = packh(p0, p1);
                af[g * 2 + (nt >> 1)][(nt & 1) * 2 + 1] = packh(p2, p3);
            }
        }

        // ---- O += P @ V ; l += P @ ones ----
        #pragma unroll
        for (int kt = 0; kt < 4; kt++) {
            uint32_t bv[4][4];
            #pragma unroll
            for (int dh = 0; dh < 4; dh++) {
                const int row = kt * 16 + v_row;
                LDM_X4T(bv[dh][0], bv[dh][1], bv[dh][2], bv[dh][3],
                        vbase + SWZ(row * 128 + dh * 32 + v_bc));
            }
            #pragma unroll
            for (int dt = 0; dt < 8; dt++)
                mmah(acc[dt], af[kt][0], af[kt][1], af[kt][2], af[kt][3],
                     bv[dt >> 1][(dt & 1) * 2], bv[dt >> 1][(dt & 1) * 2 + 1]);
            mmah(lacc, af[kt][0], af[kt][1], af[kt][2], af[kt][3],
                 ONESH2, ONESH2);
        }
    }

    // ---- l is fully reduced per-row in lacc (ones-B mma); normalize ----
    const float linv0 = 1.f / lacc[0];
    const float linv1 = 1.f / lacc[2];

    const int r0 = q0 + warp * 16 + gid;
    #pragma unroll
    for (int dt = 0; dt < 8; dt++) {
        const int col = dt * 8 + 2 * tig;
        const size_t o0 = ((size_t)(b * Nd + r0)) * Cd + h * HDd + col;
        const size_t o1 = ((size_t)(b * Nd + r0 + 8)) * Cd + h * HDd + col;
        *(uint32_t*)&g_aoh[o0] = packh(acc[dt][0] * linv0, acc[dt][1] * linv0);
        *(uint32_t*)&g_aoh[o1] = packh(acc[dt][2] * linv1, acc[dt][3] * linv1);
    }
}

// ---------------- k mean over heads (half2-vectorized) ----------------------
__global__ __launch_bounds__(256)
void kmean_kernel(float* __restrict__ out)
{
    const int i2 = blockIdx.x * 256 + threadIdx.x;      // over B*N*HD/2
    if (i2 >= Bd * Nd * HDd / 2) return;
    const int idx = i2 * 2;
    const int hd = idx & 63;
    const int n  = (idx >> 6) & 2047;
    const int b  = idx >> 17;
    float s0 = 0.f, s1 = 0.f;
    #pragma unroll
    for (int h = 0; h < Hd; h++) {
        const __half2 v = *(const __half2*)&g_kh[(((size_t)(b * Hd + h)) * Nd + n) * HDd + hd];
        const float2 f = __half22float2(v);
        s0 += f.x; s1 += f.y;
    }
    *(float2*)&out[idx] = make_float2(s0 * (1.0f / Hd), s1 * (1.0f / Hd));
}

// ---------------- launch ----------------------------------------------------
extern "C" void kernel_launch(void* const* d_in, const int* in_sizes, int n_in,
                              void* d_out, int out_size)
{
    const float* x    = (const float*)d_in[0];
    const float* size = (const float*)d_in[1];
    const float* q_w  = (const float*)d_in[2];
    const float* q_b  = (const float*)d_in[3];
    const float* k_w  = (const float*)d_in[4];
    const float* k_b  = (const float*)d_in[5];
    const float* v_w  = (const float*)d_in[6];
    const float* v_b  = (const float*)d_in[7];
    const float* o_w  = (const float*)d_in[8];
    const float* o_b  = (const float*)d_in[9];

    float* out   = (float*)d_out;
    float* kmean = out + (size_t)Bd * Nd * Cd;

    cudaFuncSetAttribute(attn_fa2, cudaFuncAttributeMaxDynamicSharedMemorySize, ASMB);
    cudaFuncSetAttribute(gemm_qkv_h2, cudaFuncAttributeMaxDynamicSharedMemorySize, GSMB);
    cudaFuncSetAttribute(gemm_o_h2, cudaFuncAttributeMaxDynamicSharedMemorySize, GSMB);

    __half* xh_p;  cudaGetSymbolAddress((void**)&xh_p, g_xh);
    __half* wh_p;  cudaGetSymbolAddress((void**)&wh_p, g_wh);
    float*  ls_p;  cudaGetSymbolAddress((void**)&ls_p, g_lsz);

    const long long ntot = (long long)NX + 4LL * NW + NS;
    cvt_all_kernel<<<(unsigned)((ntot / 8 + 255) / 256), 256>>>(
        x, q_w, k_w, v_w, o_w, size, xh_p, wh_p, ls_p);

    dim3 gqkv(Cd / 128, (Bd * Nd) / 128, 3);
    gemm_qkv_h2<<<gqkv, 256, GSMB>>>(q_b, k_b, v_b);

    kmean_kernel<<<(Bd * Nd * HDd / 2 + 255) / 256, 256>>>(kmean);

    dim3 gat(Bd * Hd, Nd / 128);
    attn_fa2<<<gat, 256, ASMB>>>(ls_p);

    dim3 go(Cd / 128, (Bd * Nd) / 128, 1);
    gemm_o_h2<<<go, 256, GSMB>>>(o_b, out);
}